// round 13
// baseline (speedup 1.0000x reference)
#include <cuda_runtime.h>
#include <cuda_bf16.h>
#include <cuda_fp16.h>
#include <math.h>
#include <stdint.h>

#define BB 2
#define LL 4096
#define DD 1024
#define DIN 2048
#define DSTATE 128
#define NH 32
#define HD 64
#define CONVDIM 2304
#define DPROJ 4384
#define NPADPROJ 4480
#define NCHUNK 8
#define CHL (LL / NCHUNK)

// scan chunking
#define SC_T 16
#define CKN 16            // chunks along L
#define CKL (LL / CKN)    // 256 steps per chunk
#define NBLK1 (BB * NH * 2 * CKN)  // 2048 phase-1/3 blocks

// ---------------- scratch (device globals) ----------------
__device__ float g_zx[BB * LL * DPROJ];
__device__ float g_conv[BB * LL * CONVDIM];
__device__ float g_dt[BB * LL * NH];
__device__ float g_dA[BB * LL * NH];
__device__ float g_y1[BB * LL * DIN];
__device__ float g_y2[BB * LL * DIN];
__device__ float g_PQ[BB * LL * 2 * DD];
__device__ float g_R[BB * LL * DD];
__device__ float g_Wz[DD * DD];
__device__ float g_Wc[DD * DD];
__device__ float g_cs[BB * NCHUNK * DD];
__device__ float g_Send[NBLK1 * 4096];
__device__ float g_Sstart[NBLK1 * 4096];
__device__ float g_prod[BB * NH * LL];

__device__ __half g_xnh[BB * LL * DD];
__device__ __half g_Wpt[NPADPROJ * DD];
__device__ __half g_Fzt[DD * DIN];
__device__ __half g_Fot[DD * DIN];
__device__ __half g_Fmt[DD * DIN];
__device__ __half g_zw[DD * DIN];
__device__ __half g_ow[DD * DIN];
__device__ __half g_Wpq[2 * DD * DD];
__device__ __half g_yh[BB * LL * DIN];

// ---------------- helpers ----------------
__device__ __forceinline__ uint32_t s2u(const void* p) {
    uint32_t a;
    asm("{ .reg .u64 t; cvta.to.shared.u64 t, %1; cvt.u32.u64 %0, t; }" : "=r"(a) : "l"(p));
    return a;
}

#define LDSM4(r0, r1, r2, r3, addr)                                                         \
    asm volatile("ldmatrix.sync.aligned.m8n8.x4.shared.b16 {%0,%1,%2,%3}, [%4];"            \
                 : "=r"(r0), "=r"(r1), "=r"(r2), "=r"(r3) : "r"(addr))

#define MMA16816H(c, a, b)                                                                  \
    asm volatile("mma.sync.aligned.m16n8k16.row.col.f32.f16.f16.f32 "                       \
                 "{%0,%1,%2,%3}, {%4,%5,%6,%7}, {%8,%9}, {%0,%1,%2,%3};"                    \
                 : "+f"((c)[0]), "+f"((c)[1]), "+f"((c)[2]), "+f"((c)[3])                   \
                 : "r"((a)[0]), "r"((a)[1]), "r"((a)[2]), "r"((a)[3]),                      \
                   "r"((b)[0]), "r"((b)[1]))

__inline__ __device__ float blockReduceSum(float v) {
    __shared__ float sh[32];
    int lane = threadIdx.x & 31, wid = threadIdx.x >> 5;
#pragma unroll
    for (int o = 16; o > 0; o >>= 1) v += __shfl_down_sync(0xffffffffu, v, o);
    if (lane == 0) sh[wid] = v;
    __syncthreads();
    v = (threadIdx.x < (blockDim.x >> 5)) ? sh[lane] : 0.f;
    if (wid == 0) {
#pragma unroll
        for (int o = 16; o > 0; o >>= 1) v += __shfl_down_sync(0xffffffffu, v, o);
        if (lane == 0) sh[0] = v;
    }
    __syncthreads();
    return sh[0];
}

__inline__ __device__ float siluf(float v) { return v / (1.f + expf(-v)); }

// ---------------- rmsnorm -> fp16 ----------------
__global__ void rmsnorm_h_kernel(const float* __restrict__ x, const float* __restrict__ w,
                                 __half* __restrict__ oh) {
    size_t row = blockIdx.x;
    const float* xr = x + row * DD;
    float ss = 0.f;
    for (int i = threadIdx.x; i < DD; i += blockDim.x) { float v = xr[i]; ss += v * v; }
    ss = blockReduceSum(ss);
    float inv = rsqrtf(ss / (float)DD + 1e-5f);
    for (int i = threadIdx.x; i < DD; i += blockDim.x)
        oh[row * DD + i] = __float2half(xr[i] * inv * w[i]);
}

// ---------------- transpose -> fp16 ----------------
__global__ void transpose_h_kernel(const float* __restrict__ src, int K, int N,
                                   __half* __restrict__ out, int Npad) {
    __shared__ float tile[32][33];
    int k0 = blockIdx.x * 32, n0 = blockIdx.y * 32;
#pragma unroll
    for (int i = 0; i < 4; i++) {
        int k = k0 + threadIdx.y + i * 8;
        int n = n0 + threadIdx.x;
        float v = (k < K && n < N) ? src[(size_t)k * N + n] : 0.f;
        tile[threadIdx.y + i * 8][threadIdx.x] = v;
    }
    __syncthreads();
#pragma unroll
    for (int i = 0; i < 4; i++) {
        int n = n0 + threadIdx.y + i * 8;
        int k = k0 + threadIdx.x;
        if (n < Npad && k < K)
            out[(size_t)n * K + k] = __float2half(tile[threadIdx.x][threadIdx.y + i * 8]);
    }
}

// ---------------- elementwise to fp16 ----------------
__global__ void tohalf_kernel(const float* __restrict__ src, __half* __restrict__ oh, size_t n) {
    size_t i = (size_t)blockIdx.x * blockDim.x + threadIdx.x;
    if (i >= n) return;
    oh[i] = __float2half(src[i]);
}

// ---------------- fp16 single-pass mma GEMM with column offset ----------------
#define TG_STAGE_BYTES 16384
#define TG_STAGES 4
#define TG_SMEM (TG_STAGES * TG_STAGE_BYTES)

__global__ __launch_bounds__(256, 2) void tgemm_kernel(const __half* __restrict__ A,
                                                       const __half* __restrict__ B,
                                                       float* __restrict__ C, int M, int N, int K,
                                                       int nbase) {
    extern __shared__ char smg[];
    uint32_t sb = s2u(smg);
    const int tid = threadIdx.x;
    const int wid = tid >> 5, lid = tid & 31;
    const int m0 = blockIdx.y * 128, n0 = blockIdx.x * 128 + nbase;
    const int wm = wid & 1, wn = wid >> 1;
    const int lr = lid & 15, lu = lid >> 4;
    const int NKC = K >> 5;

    const __half* gsrc[4];
    uint32_t dsto[4];
#pragma unroll
    for (int i = 0; i < 4; i++) {
        int q = tid + i * 256;
        int arr = q >> 9, idx = q & 511, row = idx >> 2, u = idx & 3;
        const __half* base = (arr == 0) ? A : B;
        int grow = ((arr == 0) ? m0 : n0) + row;
        gsrc[i] = base + (size_t)grow * K + u * 8;
        dsto[i] = (uint32_t)(arr * 8192 + row * 64 + ((u ^ (row & 3)) << 4));
    }

    auto issue = [&](int kc, int buf) {
        uint32_t sbuf = sb + buf * TG_STAGE_BYTES;
#pragma unroll
        for (int i = 0; i < 4; i++)
            asm volatile("cp.async.cg.shared.global [%0], [%1], 16;" ::
                         "r"(sbuf + dsto[i]), "l"((const void*)(gsrc[i] + (size_t)kc * 32))
                         : "memory");
    };

    float acc[4][4][4];
#pragma unroll
    for (int a = 0; a < 4; a++)
#pragma unroll
        for (int b = 0; b < 4; b++)
#pragma unroll
            for (int c = 0; c < 4; c++) acc[a][b][c] = 0.f;

    issue(0, 0);
    asm volatile("cp.async.commit_group;" ::: "memory");
    issue(1, 1);
    asm volatile("cp.async.commit_group;" ::: "memory");
    issue(2, 2);
    asm volatile("cp.async.commit_group;" ::: "memory");

    for (int kc = 0; kc < NKC; kc++) {
        asm volatile("cp.async.wait_group 2;" ::: "memory");
        __syncthreads();
        int nk = kc + 3;
        if (nk < NKC) issue(nk, nk & 3);
        asm volatile("cp.async.commit_group;" ::: "memory");

        uint32_t ab = sb + (kc & 3) * TG_STAGE_BYTES;
#pragma unroll
        for (int s = 0; s < 2; s++) {
            uint32_t af[4][4], bf[4][2];
#pragma unroll
            for (int mt = 0; mt < 4; mt++) {
                int r = wm * 64 + mt * 16 + lr;
                int u = 2 * s + lu;
                uint32_t ad = ab + r * 64 + ((u ^ (r & 3)) << 4);
                LDSM4(af[mt][0], af[mt][1], af[mt][2], af[mt][3], ad);
            }
#pragma unroll
            for (int p = 0; p < 2; p++) {
                int r = wn * 32 + p * 16 + lr;
                int u = 2 * s + lu;
                uint32_t bd = ab + 8192 + r * 64 + ((u ^ (r & 3)) << 4);
                uint32_t t0, t1, t2, t3;
                LDSM4(t0, t1, t2, t3, bd);
                bf[p * 2 + 0][0] = t0; bf[p * 2 + 0][1] = t2;
                bf[p * 2 + 1][0] = t1; bf[p * 2 + 1][1] = t3;
            }
#pragma unroll
            for (int mt = 0; mt < 4; mt++)
#pragma unroll
                for (int nt = 0; nt < 4; nt++)
                    MMA16816H(acc[mt][nt], af[mt], bf[nt]);
        }
    }

#pragma unroll
    for (int mt = 0; mt < 4; mt++) {
        int r = m0 + wm * 64 + mt * 16 + (lid >> 2);
#pragma unroll
        for (int nt = 0; nt < 4; nt++) {
            int n = n0 + wn * 32 + nt * 8 + (lid & 3) * 2;
            if (n < N) {
                *(float2*)&C[(size_t)r * N + n] = make_float2(acc[mt][nt][0], acc[mt][nt][1]);
                *(float2*)&C[(size_t)(r + 8) * N + n] = make_float2(acc[mt][nt][2], acc[mt][nt][3]);
            }
        }
    }
}

// ---------------- conv + silu ----------------
__global__ void conv_kernel(const float* __restrict__ zx, const float* __restrict__ cw,
                            const float* __restrict__ cb, float* __restrict__ out) {
    size_t idx = (size_t)blockIdx.x * blockDim.x + threadIdx.x;
    if (idx >= (size_t)BB * LL * CONVDIM) return;
    int c = idx % CONVDIM;
    size_t rest = idx / CONVDIM;
    int t = rest % LL;
    int b = rest / LL;
    float acc = cb[c];
#pragma unroll
    for (int k = 0; k < 4; k++) {
        int tt = t - 3 + k;
        if (tt >= 0)
            acc += zx[((size_t)b * LL + tt) * DPROJ + DIN + c] * cw[k * CONVDIM + c];
    }
    out[idx] = siluf(acc);
}

// ---------------- dt softplus + dA ----------------
__global__ void dtda_kernel(const float* __restrict__ zx, const float* __restrict__ dtb,
                            const float* __restrict__ alog, float* __restrict__ dtO,
                            float* __restrict__ dAO) {
    size_t idx = (size_t)blockIdx.x * blockDim.x + threadIdx.x;
    if (idx >= (size_t)BB * LL * NH) return;
    int h = idx % NH;
    size_t row = idx / NH;
    float raw = zx[row * DPROJ + (DPROJ - NH) + h] + dtb[h];
    float sp = (raw > 20.f) ? raw : log1pf(expf(raw));
    dtO[idx] = sp;
    dAO[idx] = expf(sp * (-expf(alog[h])));
}

// ---------------- Phase 1: local scan per chunk ----------------
// grid NBLK1=2048: ck=bid&15, s=(bid>>4)&1, h=(bid>>5)&31, b=bid>>10. 512 threads.
__global__ __launch_bounds__(512, 3) void scan_p1_kernel(const float* __restrict__ conv,
                                                         const float* __restrict__ dtp,
                                                         const float* __restrict__ dAp,
                                                         float* __restrict__ yp0,
                                                         float* __restrict__ yp1,
                                                         float* __restrict__ Send,
                                                         float* __restrict__ prodb) {
    const int ck = blockIdx.x & 15;
    const int s = (blockIdx.x >> 4) & 1;
    const int h = (blockIdx.x >> 5) & 31;
    const int b = blockIdx.x >> 10;
    float* __restrict__ yp = s ? yp1 : yp0;
    const int n0 = s * 64;
    const int tid = threadIdx.x;
    const int p = tid >> 3, ln = tid & 7;
    const int mc0 = ck * (CKL / SC_T);  // 16 microchunks per chunk

    __shared__ __align__(16) float sB[3][SC_T][64];
    __shared__ __align__(16) float sC[3][SC_T][64];
    __shared__ __align__(16) float sx[3][SC_T][64];
    __shared__ float sdt[3][SC_T], sdA[3][SC_T];

    auto load = [&](int mc, int st) {
#pragma unroll
        for (int q = tid; q < 800; q += 512) {
            if (q < 768) {
                int t = q / 48, k = q % 48;
                int arr = k >> 4, o = (k & 15) * 4;
                size_t g = (size_t)b * LL + (size_t)mc * SC_T + t;
                const float* src;
                uint32_t d;
                if (arr == 0) { src = conv + g * CONVDIM + 2048 + n0 + o; d = s2u(&sB[st][t][o]); }
                else if (arr == 1) { src = conv + g * CONVDIM + 2176 + n0 + o; d = s2u(&sC[st][t][o]); }
                else { src = conv + g * CONVDIM + h * HD + o; d = s2u(&sx[st][t][o]); }
                asm volatile("cp.async.cg.shared.global [%0], [%1], 16;" :: "r"(d), "l"((const void*)src) : "memory");
            } else if (q < 784) {
                int t = q - 768;
                size_t g = (size_t)b * LL + (size_t)mc * SC_T + t;
                uint32_t d = s2u(&sdt[st][t]);
                asm volatile("cp.async.ca.shared.global [%0], [%1], 4;" :: "r"(d), "l"((const void*)(dtp + g * NH + h)) : "memory");
            } else {
                int t = q - 784;
                size_t g = (size_t)b * LL + (size_t)mc * SC_T + t;
                uint32_t d = s2u(&sdA[st][t]);
                asm volatile("cp.async.ca.shared.global [%0], [%1], 4;" :: "r"(d), "l"((const void*)(dAp + g * NH + h)) : "memory");
            }
        }
    };

    float S[8];
#pragma unroll
    for (int j = 0; j < 8; j++) S[j] = 0.f;
    float pa = 1.f;
    const bool doprod = (s == 0 && tid == 0);
    const size_t prbase = (size_t)(b * NH + h) * LL + (size_t)ck * CKL;

    load(mc0, 0);
    asm volatile("cp.async.commit_group;" ::: "memory");
    load(mc0 + 1, 1);
    asm volatile("cp.async.commit_group;" ::: "memory");

    for (int c = 0; c < CKL / SC_T; c++) {
        asm volatile("cp.async.wait_group 1;" ::: "memory");
        __syncthreads();
        if (c + 2 < CKL / SC_T) load(mc0 + c + 2, (c + 2) % 3);
        asm volatile("cp.async.commit_group;" ::: "memory");

        const int st = c % 3;
        size_t gbase = ((size_t)b * LL + (size_t)(mc0 + c) * SC_T) * DIN + h * HD + p;
#pragma unroll
        for (int t = 0; t < SC_T; t++) {
            float a = sdA[st][t];
            float dv = sdt[st][t];
            float xv = sx[st][t][p];
            float dtx = dv * xv;
            pa *= a;
            float4 b0 = *(float4*)&sB[st][t][ln * 8];
            float4 b1 = *(float4*)&sB[st][t][ln * 8 + 4];
            float4 c0 = *(float4*)&sC[st][t][ln * 8];
            float4 c1 = *(float4*)&sC[st][t][ln * 8 + 4];
            S[0] = fmaf(S[0], a, dtx * b0.x);
            S[1] = fmaf(S[1], a, dtx * b0.y);
            S[2] = fmaf(S[2], a, dtx * b0.z);
            S[3] = fmaf(S[3], a, dtx * b0.w);
            S[4] = fmaf(S[4], a, dtx * b1.x);
            S[5] = fmaf(S[5], a, dtx * b1.y);
            S[6] = fmaf(S[6], a, dtx * b1.z);
            S[7] = fmaf(S[7], a, dtx * b1.w);
            float part = S[0] * c0.x;
            part = fmaf(S[1], c0.y, part);
            part = fmaf(S[2], c0.z, part);
            part = fmaf(S[3], c0.w, part);
            part = fmaf(S[4], c1.x, part);
            part = fmaf(S[5], c1.y, part);
            part = fmaf(S[6], c1.z, part);
            part = fmaf(S[7], c1.w, part);
            part += __shfl_down_sync(0xffffffffu, part, 4, 8);
            part += __shfl_down_sync(0xffffffffu, part, 2, 8);
            part += __shfl_down_sync(0xffffffffu, part, 1, 8);
            if (ln == 0) yp[gbase + (size_t)t * DIN] = part;
            if (doprod) prodb[prbase + (size_t)c * SC_T + t] = pa;
        }
    }
    // store chunk-final state
    size_t so = (size_t)blockIdx.x * 4096 + (size_t)tid * 8;
#pragma unroll
    for (int j = 0; j < 8; j += 4)
        *(float4*)&Send[so + j] = make_float4(S[j], S[j + 1], S[j + 2], S[j + 3]);
}

// ---------------- Phase 2: combine chunk states -> S_start per chunk ----------------
// grid 128: s=bid&1, h=(bid>>1)&31, b=bid>>6. 512 threads, each owns 8 floats.
__global__ void scan_p2_kernel(const float* __restrict__ Send, const float* __restrict__ prodb,
                               float* __restrict__ Sstart) {
    int s = blockIdx.x & 1, h = (blockIdx.x >> 1) & 31, b = blockIdx.x >> 6;
    int tid = threadIdx.x;
    int base_bid = ((b * NH + h) * 2 + s) * CKN;
    size_t prbase = (size_t)(b * NH + h) * LL;
    float acc[8];
#pragma unroll
    for (int j = 0; j < 8; j++) acc[j] = 0.f;
    for (int ck = 0; ck < CKN; ck++) {
        size_t o = (size_t)(base_bid + ck) * 4096 + (size_t)tid * 8;
        *(float4*)&Sstart[o] = make_float4(acc[0], acc[1], acc[2], acc[3]);
        *(float4*)&Sstart[o + 4] = make_float4(acc[4], acc[5], acc[6], acc[7]);
        float pc = prodb[prbase + (size_t)ck * CKL + (CKL - 1)];
        float4 e0 = *(const float4*)&Send[o];
        float4 e1 = *(const float4*)&Send[o + 4];
        acc[0] = fmaf(acc[0], pc, e0.x);
        acc[1] = fmaf(acc[1], pc, e0.y);
        acc[2] = fmaf(acc[2], pc, e0.z);
        acc[3] = fmaf(acc[3], pc, e0.w);
        acc[4] = fmaf(acc[4], pc, e1.x);
        acc[5] = fmaf(acc[5], pc, e1.y);
        acc[6] = fmaf(acc[6], pc, e1.z);
        acc[7] = fmaf(acc[7], pc, e1.w);
    }
}

// ---------------- Phase 3: cross-chunk correction y += prod_t * (C_t . S_start) ----------------
// grid NBLK1; blocks with ck==0 exit (S_start = 0). 512 threads: tg=tid>>3 (4 t's), pp=tid&7 (8 p's).
#define P3_CPAD 68
#define P3_SMEMF (64 * P3_CPAD + 256 * P3_CPAD + 256)
#define P3_SMEMB (P3_SMEMF * 4)

__global__ __launch_bounds__(512, 1) void scan_p3_kernel(const float* __restrict__ conv,
                                                         const float* __restrict__ Sstart,
                                                         const float* __restrict__ prodb,
                                                         float* __restrict__ yp0,
                                                         float* __restrict__ yp1) {
    const int ck = blockIdx.x & 15;
    if (ck == 0) return;
    const int s = (blockIdx.x >> 4) & 1;
    const int h = (blockIdx.x >> 5) & 31;
    const int b = blockIdx.x >> 10;
    float* __restrict__ yp = s ? yp1 : yp0;
    const int n0 = s * 64;
    const int tid = threadIdx.x;

    extern __shared__ float p3s[];
    float* Ss = p3s;                      // [64][P3_CPAD]
    float* Cs = p3s + 64 * P3_CPAD;       // [256][P3_CPAD]
    float* pr = Cs + 256 * P3_CPAD;       // [256]

    // load S_start (4096 floats)
    size_t ssb = (size_t)blockIdx.x * 4096;
    for (int q = tid; q < 1024; q += 512) {
        int row = q >> 4, quad = q & 15;
        float4 v = *(const float4*)&Sstart[ssb + (size_t)row * 64 + quad * 4];
        *(float4*)&Ss[row * P3_CPAD + quad * 4] = v;
    }
    // load prod
    size_t prb = (size_t)(b * NH + h) * LL + (size_t)ck * CKL;
    if (tid < 256) pr[tid] = prodb[prb + tid];
    // load C rows
    size_t t0row = (size_t)b * LL + (size_t)ck * CKL;
    for (int q = tid; q < 4096; q += 512) {
        int tt = q >> 4, quad = q & 15;
        float4 v = *(const float4*)(conv + (t0row + tt) * CONVDIM + 2176 + n0 + quad * 4);
        *(float4*)&Cs[tt * P3_CPAD + quad * 4] = v;
    }
    __syncthreads();

    const int tg = tid >> 3;   // t = tg*4 + i
    const int pp = tid & 7;    // p = pp*8 + k
    float acc[4][8];
#pragma unroll
    for (int i = 0; i < 4; i++)
#pragma unroll
        for (int k = 0; k < 8; k++) acc[i][k] = 0.f;

#pragma unroll
    for (int quad = 0; quad < 16; quad++) {
        float4 cv[4], sv[8];
#pragma unroll
        for (int i = 0; i < 4; i++) cv[i] = *(float4*)&Cs[(tg * 4 + i) * P3_CPAD + quad * 4];
#pragma unroll
        for (int k = 0; k < 8; k++) sv[k] = *(float4*)&Ss[(pp * 8 + k) * P3_CPAD + quad * 4];
#pragma unroll
        for (int i = 0; i < 4; i++)
#pragma unroll
            for (int k = 0; k < 8; k++) {
                acc[i][k] = fmaf(cv[i].x, sv[k].x, acc[i][k]);
                acc[i][k] = fmaf(cv[i].y, sv[k].y, acc[i][k]);
                acc[i][k] = fmaf(cv[i].z, sv[k].z, acc[i][k]);
                acc[i][k] = fmaf(cv[i].w, sv[k].w, acc[i][k]);
            }
    }

#pragma unroll
    for (int i = 0; i < 4; i++) {
        int tl = tg * 4 + i;
        float pt = pr[tl];
        size_t yo = ((size_t)b * LL + (size_t)ck * CKL + tl) * DIN + h * HD + pp * 8;
        float4 y0 = *(float4*)&yp[yo];
        float4 y1v = *(float4*)&yp[yo + 4];
        y0.x = fmaf(pt, acc[i][0], y0.x);
        y0.y = fmaf(pt, acc[i][1], y0.y);
        y0.z = fmaf(pt, acc[i][2], y0.z);
        y0.w = fmaf(pt, acc[i][3], y0.w);
        y1v.x = fmaf(pt, acc[i][4], y1v.x);
        y1v.y = fmaf(pt, acc[i][5], y1v.y);
        y1v.z = fmaf(pt, acc[i][6], y1v.z);
        y1v.w = fmaf(pt, acc[i][7], y1v.w);
        *(float4*)&yp[yo] = y0;
        *(float4*)&yp[yo + 4] = y1v;
    }
}

// ---------------- gated rmsnorm -> fp16 ----------------
__global__ void gnorm_h_kernel(const float* __restrict__ y1, const float* __restrict__ y2,
                               const float* __restrict__ conv, const float* __restrict__ Dp,
                               const float* __restrict__ zx, const float* __restrict__ gw,
                               __half* __restrict__ oh) {
    size_t row = blockIdx.x;
    const float* zr = zx + row * DPROJ;
    float v[8];
    float ss = 0.f;
#pragma unroll
    for (int u = 0; u < 8; u++) {
        int i = threadIdx.x + u * 256;
        float xv = conv[row * CONVDIM + i];
        float yv = y1[row * DIN + i] + y2[row * DIN + i] + Dp[i >> 6] * xv;
        float z = zr[i];
        float val = yv * siluf(z);
        v[u] = val;
        ss += val * val;
    }
    ss = blockReduceSum(ss);
    float inv = rsqrtf(ss / (float)DIN + 1e-5f);
#pragma unroll
    for (int u = 0; u < 8; u++) {
        int i = threadIdx.x + u * 256;
        oh[row * DIN + i] = __float2half(v[u] * inv * gw[i]);
    }
}

// ---------------- cumsum passes (over Q = PQ[:,1024:2048]) ----------------
__global__ void chunk_sum_kernel(const float* __restrict__ PQ, float* __restrict__ cs) {
    int c = (blockIdx.x & 3) * 256 + threadIdx.x;
    int chunk = (blockIdx.x >> 2) & (NCHUNK - 1);
    int b = blockIdx.x >> 5;
    float s = 0.f;
    size_t base = ((size_t)b * LL + (size_t)chunk * CHL) * (2 * DD) + DD + c;
    for (int l = 0; l < CHL; l++) s += PQ[base + (size_t)l * (2 * DD)];
    cs[((size_t)b * NCHUNK + chunk) * DD + c] = s;
}

__global__ void scan_chunks_kernel(float* __restrict__ cs) {
    int i = blockIdx.x * blockDim.x + threadIdx.x;
    if (i >= BB * DD) return;
    int b = i / DD, c = i % DD;
    float acc = 0.f;
#pragma unroll
    for (int ch = 0; ch < NCHUNK; ch++) {
        size_t o = ((size_t)b * NCHUNK + ch) * DD + c;
        float v = cs[o];
        cs[o] = acc;
        acc += v;
    }
}

__global__ void final_kernel(const float* __restrict__ x, const float* __restrict__ PQ,
                             const float* __restrict__ R,
                             const float* __restrict__ cs, float* __restrict__ out) {
    int c = (blockIdx.x & 3) * 256 + threadIdx.x;
    int chunk = (blockIdx.x >> 2) & (NCHUNK - 1);
    int b = blockIdx.x >> 5;
    float acc = cs[((size_t)b * NCHUNK + chunk) * DD + c];
    size_t rbase = ((size_t)b * LL + (size_t)chunk * CHL) * DD + c;
    size_t pqbase = ((size_t)b * LL + (size_t)chunk * CHL) * (2 * DD) + c;
    for (int l = 0; l < CHL; l++) {
        size_t idx = rbase + (size_t)l * DD;
        size_t pqi = pqbase + (size_t)l * (2 * DD);
        acc += PQ[pqi + DD];
        out[idx] = x[idx] + PQ[pqi] + R[idx] + acc;
    }
}

// ---------------- launch ----------------
extern "C" void kernel_launch(void* const* d_in, const int* in_sizes, int n_in,
                              void* d_out, int out_size) {
    const float* x       = (const float*)d_in[0];
    const float* norm_w  = (const float*)d_in[1];
    const float* in_proj = (const float*)d_in[2];
    const float* conv_W  = (const float*)d_in[3];
    const float* conv_b  = (const float*)d_in[4];
    const float* dt_bias = (const float*)d_in[5];
    const float* A_log   = (const float*)d_in[6];
    const float* Dvec    = (const float*)d_in[7];
    const float* gnorm_w = (const float*)d_in[8];
    const float* zero_W  = (const float*)d_in[9];
    const float* one_W   = (const float*)d_in[10];
    const float* fusion  = (const float*)d_in[11];
    float* out = (float*)d_out;

    float *zx, *conv, *dt, *dA, *y1, *y2, *PQ, *R, *Wz, *Wc, *cs, *Send, *Sstart, *prodb;
    __half *xnh, *Wpt, *Fzt, *Fot, *Fmt, *zw, *ow, *Wpq, *yh;
    cudaGetSymbolAddress((void**)&zx, g_zx);
    cudaGetSymbolAddress((void**)&conv, g_conv);
    cudaGetSymbolAddress((void**)&dt, g_dt);
    cudaGetSymbolAddress((void**)&dA, g_dA);
    cudaGetSymbolAddress((void**)&y1, g_y1);
    cudaGetSymbolAddress((void**)&y2, g_y2);
    cudaGetSymbolAddress((void**)&PQ, g_PQ);
    cudaGetSymbolAddress((void**)&R, g_R);
    cudaGetSymbolAddress((void**)&Wz, g_Wz);
    cudaGetSymbolAddress((void**)&Wc, g_Wc);
    cudaGetSymbolAddress((void**)&cs, g_cs);
    cudaGetSymbolAddress((void**)&Send, g_Send);
    cudaGetSymbolAddress((void**)&Sstart, g_Sstart);
    cudaGetSymbolAddress((void**)&prodb, g_prod);
    cudaGetSymbolAddress((void**)&xnh, g_xnh);
    cudaGetSymbolAddress((void**)&Wpt, g_Wpt);
    cudaGetSymbolAddress((void**)&Fzt, g_Fzt);
    cudaGetSymbolAddress((void**)&Fot, g_Fot);
    cudaGetSymbolAddress((void**)&Fmt, g_Fmt);
    cudaGetSymbolAddress((void**)&zw, g_zw);
    cudaGetSymbolAddress((void**)&ow, g_ow);
    cudaGetSymbolAddress((void**)&Wpq, g_Wpq);
    cudaGetSymbolAddress((void**)&yh, g_yh);

    const int M = BB * LL;
    cudaFuncSetAttribute(tgemm_kernel, cudaFuncAttributeMaxDynamicSharedMemorySize, TG_SMEM);
    cudaFuncSetAttribute(scan_p3_kernel, cudaFuncAttributeMaxDynamicSharedMemorySize, P3_SMEMB);

    cudaStream_t s2;
    cudaEvent_t ev0, evA, evB;
    cudaStreamCreateWithFlags(&s2, cudaStreamNonBlocking);
    cudaEventCreateWithFlags(&ev0, cudaEventDisableTiming);
    cudaEventCreateWithFlags(&evA, cudaEventDisableTiming);
    cudaEventCreateWithFlags(&evB, cudaEventDisableTiming);

    dim3 tb(32, 8);

    // ---- main: shared prep ----
    rmsnorm_h_kernel<<<M, 256>>>(x, norm_w, xnh);
    transpose_h_kernel<<<dim3(DD / 32, NPADPROJ / 32), tb>>>(in_proj, DD, DPROJ, Wpt, NPADPROJ);
    transpose_h_kernel<<<dim3(DIN / 32, DD / 32), tb>>>(fusion, DIN, DD, Fmt, DD);
    cudaEventRecord(ev0, 0);

    // ---- main: xBC+dt half of zx, conv, dtda ----
    tgemm_kernel<<<dim3((NPADPROJ - 2048) / 128, M / 128), 256, TG_SMEM>>>(xnh, Wpt, zx, M, DPROJ, DD, 2048);
    {
        size_t tot = (size_t)BB * LL * CONVDIM;
        conv_kernel<<<(unsigned)((tot + 255) / 256), 256>>>(zx, conv_W, conv_b, conv);
        size_t tot2 = (size_t)BB * LL * NH;
        dtda_kernel<<<(unsigned)((tot2 + 255) / 256), 256>>>(zx, dt_bias, A_log, dt, dA);
    }
    cudaEventRecord(evA, 0);

    // ---- side: z half of zx, then 3-phase scan -> gnorm -> R ----
    cudaStreamWaitEvent(s2, ev0, 0);
    tgemm_kernel<<<dim3(2048 / 128, M / 128), 256, TG_SMEM, s2>>>(xnh, Wpt, zx, M, DPROJ, DD, 0);
    cudaStreamWaitEvent(s2, evA, 0);
    scan_p1_kernel<<<NBLK1, 512, 0, s2>>>(conv, dt, dA, y1, y2, Send, prodb);
    scan_p2_kernel<<<128, 512, 0, s2>>>(Send, prodb, Sstart);
    scan_p3_kernel<<<NBLK1, 512, P3_SMEMB, s2>>>(conv, Sstart, prodb, y1, y2);
    gnorm_h_kernel<<<M, 256, 0, s2>>>(y1, y2, conv, Dvec, zx, gnorm_w, yh);
    tgemm_kernel<<<dim3(8, M / 128), 256, TG_SMEM, s2>>>(yh, Fmt, R, M, DD, DIN, 0);
    cudaEventRecord(evB, s2);

    // ---- main (concurrent): combines -> PQ -> cumsum prefix ----
    {
        size_t n = (size_t)DD * DIN;
        tohalf_kernel<<<(unsigned)((n + 255) / 256), 256>>>(zero_W, zw, n);
        tohalf_kernel<<<(unsigned)((n + 255) / 256), 256>>>(one_W, ow, n);
        transpose_h_kernel<<<dim3(DIN / 32, DD / 32), tb>>>(fusion + (size_t)DIN * DD, DIN, DD, Fzt, DD);
        transpose_h_kernel<<<dim3(DIN / 32, DD / 32), tb>>>(fusion + (size_t)2 * DIN * DD, DIN, DD, Fot, DD);
    }
    tgemm_kernel<<<dim3(8, 8), 256, TG_SMEM>>>(zw, Fzt, Wz, DD, DD, DIN, 0);
    tgemm_kernel<<<dim3(8, 8), 256, TG_SMEM>>>(ow, Fot, Wc, DD, DD, DIN, 0);
    transpose_h_kernel<<<dim3(DD / 32, DD / 32), tb>>>(Wz, DD, DD, Wpq, DD);
    transpose_h_kernel<<<dim3(DD / 32, DD / 32), tb>>>(Wc, DD, DD, Wpq + (size_t)DD * DD, DD);
    tgemm_kernel<<<dim3(16, M / 128), 256, TG_SMEM>>>(xnh, Wpq, PQ, M, 2 * DD, DD, 0);
    chunk_sum_kernel<<<BB * NCHUNK * 4, 256>>>(PQ, cs);
    scan_chunks_kernel<<<(BB * DD + 255) / 256, 256>>>(cs);

    // ---- join ----
    cudaStreamWaitEvent(0, evB, 0);
    final_kernel<<<BB * NCHUNK * 4, 256>>>(x, PQ, R, cs, out);

    cudaEventDestroy(ev0);
    cudaEventDestroy(evA);
    cudaEventDestroy(evB);
    cudaStreamDestroy(s2);
}

// round 14
// speedup vs baseline: 1.0044x; 1.0044x over previous
#include <cuda_runtime.h>
#include <cuda_bf16.h>
#include <cuda_fp16.h>
#include <math.h>
#include <stdint.h>

#define BB 2
#define LL 4096
#define DD 1024
#define DIN 2048
#define DSTATE 128
#define NH 32
#define HD 64
#define CONVDIM 2304
#define DPROJ 4384
#define NPADPROJ 4480
#define NCHUNK 8
#define CHL (LL / NCHUNK)

// scan chunking
#define SC_T 16
#define CKN 8             // chunks along L
#define CKL (LL / CKN)    // 512 steps per chunk
#define NBLK1 (BB * NH * 2 * CKN)   // 1024 phase-1 blocks
#define NBLK3 (BB * NH * 2 * 16)    // 2048 phase-3 tile blocks (256 steps each)

// ---------------- scratch (device globals) ----------------
__device__ float g_zx[BB * LL * DPROJ];
__device__ float g_conv[BB * LL * CONVDIM];
__device__ float g_dt[BB * LL * NH];
__device__ float g_dA[BB * LL * NH];
__device__ float g_y1[BB * LL * DIN];
__device__ float g_y2[BB * LL * DIN];
__device__ float g_PQ[BB * LL * 2 * DD];
__device__ float g_R[BB * LL * DD];
__device__ float g_Wz[DD * DD];
__device__ float g_Wc[DD * DD];
__device__ float g_cs[BB * NCHUNK * DD];
__device__ float g_Send[NBLK1 * 4096];
__device__ float g_Sstart[NBLK1 * 4096];
__device__ float g_prod[BB * NH * LL];

__device__ __half g_xnh[BB * LL * DD];
__device__ __half g_Wpt[NPADPROJ * DD];
__device__ __half g_Fzt[DD * DIN];
__device__ __half g_Fot[DD * DIN];
__device__ __half g_Fmt[DD * DIN];
__device__ __half g_zw[DD * DIN];
__device__ __half g_ow[DD * DIN];
__device__ __half g_Wpq[2 * DD * DD];
__device__ __half g_yh[BB * LL * DIN];

// ---------------- helpers ----------------
__device__ __forceinline__ uint32_t s2u(const void* p) {
    uint32_t a;
    asm("{ .reg .u64 t; cvta.to.shared.u64 t, %1; cvt.u32.u64 %0, t; }" : "=r"(a) : "l"(p));
    return a;
}

#define LDSM4(r0, r1, r2, r3, addr)                                                         \
    asm volatile("ldmatrix.sync.aligned.m8n8.x4.shared.b16 {%0,%1,%2,%3}, [%4];"            \
                 : "=r"(r0), "=r"(r1), "=r"(r2), "=r"(r3) : "r"(addr))

#define MMA16816H(c, a, b)                                                                  \
    asm volatile("mma.sync.aligned.m16n8k16.row.col.f32.f16.f16.f32 "                       \
                 "{%0,%1,%2,%3}, {%4,%5,%6,%7}, {%8,%9}, {%0,%1,%2,%3};"                    \
                 : "+f"((c)[0]), "+f"((c)[1]), "+f"((c)[2]), "+f"((c)[3])                   \
                 : "r"((a)[0]), "r"((a)[1]), "r"((a)[2]), "r"((a)[3]),                      \
                   "r"((b)[0]), "r"((b)[1]))

__inline__ __device__ float blockReduceSum(float v) {
    __shared__ float sh[32];
    int lane = threadIdx.x & 31, wid = threadIdx.x >> 5;
#pragma unroll
    for (int o = 16; o > 0; o >>= 1) v += __shfl_down_sync(0xffffffffu, v, o);
    if (lane == 0) sh[wid] = v;
    __syncthreads();
    v = (threadIdx.x < (blockDim.x >> 5)) ? sh[lane] : 0.f;
    if (wid == 0) {
#pragma unroll
        for (int o = 16; o > 0; o >>= 1) v += __shfl_down_sync(0xffffffffu, v, o);
        if (lane == 0) sh[0] = v;
    }
    __syncthreads();
    return sh[0];
}

__inline__ __device__ float siluf(float v) { return v / (1.f + expf(-v)); }

// ---------------- rmsnorm -> fp16 ----------------
__global__ void rmsnorm_h_kernel(const float* __restrict__ x, const float* __restrict__ w,
                                 __half* __restrict__ oh) {
    size_t row = blockIdx.x;
    const float* xr = x + row * DD;
    float ss = 0.f;
    for (int i = threadIdx.x; i < DD; i += blockDim.x) { float v = xr[i]; ss += v * v; }
    ss = blockReduceSum(ss);
    float inv = rsqrtf(ss / (float)DD + 1e-5f);
    for (int i = threadIdx.x; i < DD; i += blockDim.x)
        oh[row * DD + i] = __float2half(xr[i] * inv * w[i]);
}

// ---------------- transpose -> fp16 ----------------
__global__ void transpose_h_kernel(const float* __restrict__ src, int K, int N,
                                   __half* __restrict__ out, int Npad) {
    __shared__ float tile[32][33];
    int k0 = blockIdx.x * 32, n0 = blockIdx.y * 32;
#pragma unroll
    for (int i = 0; i < 4; i++) {
        int k = k0 + threadIdx.y + i * 8;
        int n = n0 + threadIdx.x;
        float v = (k < K && n < N) ? src[(size_t)k * N + n] : 0.f;
        tile[threadIdx.y + i * 8][threadIdx.x] = v;
    }
    __syncthreads();
#pragma unroll
    for (int i = 0; i < 4; i++) {
        int n = n0 + threadIdx.y + i * 8;
        int k = k0 + threadIdx.x;
        if (n < Npad && k < K)
            out[(size_t)n * K + k] = __float2half(tile[threadIdx.x][threadIdx.y + i * 8]);
    }
}

// ---------------- elementwise to fp16 ----------------
__global__ void tohalf_kernel(const float* __restrict__ src, __half* __restrict__ oh, size_t n) {
    size_t i = (size_t)blockIdx.x * blockDim.x + threadIdx.x;
    if (i >= n) return;
    oh[i] = __float2half(src[i]);
}

// ---------------- fp16 single-pass mma GEMM with column offset ----------------
#define TG_STAGE_BYTES 16384
#define TG_STAGES 4
#define TG_SMEM (TG_STAGES * TG_STAGE_BYTES)

__global__ __launch_bounds__(256, 2) void tgemm_kernel(const __half* __restrict__ A,
                                                       const __half* __restrict__ B,
                                                       float* __restrict__ C, int M, int N, int K,
                                                       int nbase) {
    extern __shared__ char smg[];
    uint32_t sb = s2u(smg);
    const int tid = threadIdx.x;
    const int wid = tid >> 5, lid = tid & 31;
    const int m0 = blockIdx.y * 128, n0 = blockIdx.x * 128 + nbase;
    const int wm = wid & 1, wn = wid >> 1;
    const int lr = lid & 15, lu = lid >> 4;
    const int NKC = K >> 5;

    const __half* gsrc[4];
    uint32_t dsto[4];
#pragma unroll
    for (int i = 0; i < 4; i++) {
        int q = tid + i * 256;
        int arr = q >> 9, idx = q & 511, row = idx >> 2, u = idx & 3;
        const __half* base = (arr == 0) ? A : B;
        int grow = ((arr == 0) ? m0 : n0) + row;
        gsrc[i] = base + (size_t)grow * K + u * 8;
        dsto[i] = (uint32_t)(arr * 8192 + row * 64 + ((u ^ (row & 3)) << 4));
    }

    auto issue = [&](int kc, int buf) {
        uint32_t sbuf = sb + buf * TG_STAGE_BYTES;
#pragma unroll
        for (int i = 0; i < 4; i++)
            asm volatile("cp.async.cg.shared.global [%0], [%1], 16;" ::
                         "r"(sbuf + dsto[i]), "l"((const void*)(gsrc[i] + (size_t)kc * 32))
                         : "memory");
    };

    float acc[4][4][4];
#pragma unroll
    for (int a = 0; a < 4; a++)
#pragma unroll
        for (int b = 0; b < 4; b++)
#pragma unroll
            for (int c = 0; c < 4; c++) acc[a][b][c] = 0.f;

    issue(0, 0);
    asm volatile("cp.async.commit_group;" ::: "memory");
    issue(1, 1);
    asm volatile("cp.async.commit_group;" ::: "memory");
    issue(2, 2);
    asm volatile("cp.async.commit_group;" ::: "memory");

    for (int kc = 0; kc < NKC; kc++) {
        asm volatile("cp.async.wait_group 2;" ::: "memory");
        __syncthreads();
        int nk = kc + 3;
        if (nk < NKC) issue(nk, nk & 3);
        asm volatile("cp.async.commit_group;" ::: "memory");

        uint32_t ab = sb + (kc & 3) * TG_STAGE_BYTES;
#pragma unroll
        for (int s = 0; s < 2; s++) {
            uint32_t af[4][4], bf[4][2];
#pragma unroll
            for (int mt = 0; mt < 4; mt++) {
                int r = wm * 64 + mt * 16 + lr;
                int u = 2 * s + lu;
                uint32_t ad = ab + r * 64 + ((u ^ (r & 3)) << 4);
                LDSM4(af[mt][0], af[mt][1], af[mt][2], af[mt][3], ad);
            }
#pragma unroll
            for (int p = 0; p < 2; p++) {
                int r = wn * 32 + p * 16 + lr;
                int u = 2 * s + lu;
                uint32_t bd = ab + 8192 + r * 64 + ((u ^ (r & 3)) << 4);
                uint32_t t0, t1, t2, t3;
                LDSM4(t0, t1, t2, t3, bd);
                bf[p * 2 + 0][0] = t0; bf[p * 2 + 0][1] = t2;
                bf[p * 2 + 1][0] = t1; bf[p * 2 + 1][1] = t3;
            }
#pragma unroll
            for (int mt = 0; mt < 4; mt++)
#pragma unroll
                for (int nt = 0; nt < 4; nt++)
                    MMA16816H(acc[mt][nt], af[mt], bf[nt]);
        }
    }

#pragma unroll
    for (int mt = 0; mt < 4; mt++) {
        int r = m0 + wm * 64 + mt * 16 + (lid >> 2);
#pragma unroll
        for (int nt = 0; nt < 4; nt++) {
            int n = n0 + wn * 32 + nt * 8 + (lid & 3) * 2;
            if (n < N) {
                *(float2*)&C[(size_t)r * N + n] = make_float2(acc[mt][nt][0], acc[mt][nt][1]);
                *(float2*)&C[(size_t)(r + 8) * N + n] = make_float2(acc[mt][nt][2], acc[mt][nt][3]);
            }
        }
    }
}

// ---------------- conv + silu ----------------
__global__ void conv_kernel(const float* __restrict__ zx, const float* __restrict__ cw,
                            const float* __restrict__ cb, float* __restrict__ out) {
    size_t idx = (size_t)blockIdx.x * blockDim.x + threadIdx.x;
    if (idx >= (size_t)BB * LL * CONVDIM) return;
    int c = idx % CONVDIM;
    size_t rest = idx / CONVDIM;
    int t = rest % LL;
    int b = rest / LL;
    float acc = cb[c];
#pragma unroll
    for (int k = 0; k < 4; k++) {
        int tt = t - 3 + k;
        if (tt >= 0)
            acc += zx[((size_t)b * LL + tt) * DPROJ + DIN + c] * cw[k * CONVDIM + c];
    }
    out[idx] = siluf(acc);
}

// ---------------- dt softplus + dA ----------------
__global__ void dtda_kernel(const float* __restrict__ zx, const float* __restrict__ dtb,
                            const float* __restrict__ alog, float* __restrict__ dtO,
                            float* __restrict__ dAO) {
    size_t idx = (size_t)blockIdx.x * blockDim.x + threadIdx.x;
    if (idx >= (size_t)BB * LL * NH) return;
    int h = idx % NH;
    size_t row = idx / NH;
    float raw = zx[row * DPROJ + (DPROJ - NH) + h] + dtb[h];
    float sp = (raw > 20.f) ? raw : log1pf(expf(raw));
    dtO[idx] = sp;
    dAO[idx] = expf(sp * (-expf(alog[h])));
}

// ---------------- Phase 1: local scan per chunk ----------------
// grid NBLK1=1024: ck=bid&7, s=(bid>>3)&1, h=(bid>>4)&31, b=bid>>9. 512 threads, 2 blocks/SM.
__global__ __launch_bounds__(512, 2) void scan_p1_kernel(const float* __restrict__ conv,
                                                         const float* __restrict__ dtp,
                                                         const float* __restrict__ dAp,
                                                         float* __restrict__ yp0,
                                                         float* __restrict__ yp1,
                                                         float* __restrict__ Send,
                                                         float* __restrict__ prodb) {
    const int ck = blockIdx.x & 7;
    const int s = (blockIdx.x >> 3) & 1;
    const int h = (blockIdx.x >> 4) & 31;
    const int b = blockIdx.x >> 9;
    float* __restrict__ yp = s ? yp1 : yp0;
    const int n0 = s * 64;
    const int tid = threadIdx.x;
    const int p = tid >> 3, ln = tid & 7;
    const int mc0 = ck * (CKL / SC_T);  // 32 microchunks per chunk

    __shared__ __align__(16) float sB[3][SC_T][64];
    __shared__ __align__(16) float sC[3][SC_T][64];
    __shared__ __align__(16) float sx[3][SC_T][64];
    __shared__ float sdt[3][SC_T], sdA[3][SC_T];

    auto load = [&](int mc, int st) {
#pragma unroll
        for (int q = tid; q < 800; q += 512) {
            if (q < 768) {
                int t = q / 48, k = q % 48;
                int arr = k >> 4, o = (k & 15) * 4;
                size_t g = (size_t)b * LL + (size_t)mc * SC_T + t;
                const float* src;
                uint32_t d;
                if (arr == 0) { src = conv + g * CONVDIM + 2048 + n0 + o; d = s2u(&sB[st][t][o]); }
                else if (arr == 1) { src = conv + g * CONVDIM + 2176 + n0 + o; d = s2u(&sC[st][t][o]); }
                else { src = conv + g * CONVDIM + h * HD + o; d = s2u(&sx[st][t][o]); }
                asm volatile("cp.async.cg.shared.global [%0], [%1], 16;" :: "r"(d), "l"((const void*)src) : "memory");
            } else if (q < 784) {
                int t = q - 768;
                size_t g = (size_t)b * LL + (size_t)mc * SC_T + t;
                uint32_t d = s2u(&sdt[st][t]);
                asm volatile("cp.async.ca.shared.global [%0], [%1], 4;" :: "r"(d), "l"((const void*)(dtp + g * NH + h)) : "memory");
            } else {
                int t = q - 784;
                size_t g = (size_t)b * LL + (size_t)mc * SC_T + t;
                uint32_t d = s2u(&sdA[st][t]);
                asm volatile("cp.async.ca.shared.global [%0], [%1], 4;" :: "r"(d), "l"((const void*)(dAp + g * NH + h)) : "memory");
            }
        }
    };

    float S[8];
#pragma unroll
    for (int j = 0; j < 8; j++) S[j] = 0.f;
    float pa = 1.f;
    const bool doprod = (s == 0 && tid == 0);
    const size_t prbase = (size_t)(b * NH + h) * LL + (size_t)ck * CKL;

    load(mc0, 0);
    asm volatile("cp.async.commit_group;" ::: "memory");
    load(mc0 + 1, 1);
    asm volatile("cp.async.commit_group;" ::: "memory");

    for (int c = 0; c < CKL / SC_T; c++) {
        asm volatile("cp.async.wait_group 1;" ::: "memory");
        __syncthreads();
        if (c + 2 < CKL / SC_T) load(mc0 + c + 2, (c + 2) % 3);
        asm volatile("cp.async.commit_group;" ::: "memory");

        const int st = c % 3;
        size_t gbase = ((size_t)b * LL + (size_t)(mc0 + c) * SC_T) * DIN + h * HD + p;
#pragma unroll
        for (int t = 0; t < SC_T; t++) {
            float a = sdA[st][t];
            float dv = sdt[st][t];
            float xv = sx[st][t][p];
            float dtx = dv * xv;
            pa *= a;
            float4 b0 = *(float4*)&sB[st][t][ln * 8];
            float4 b1 = *(float4*)&sB[st][t][ln * 8 + 4];
            float4 c0 = *(float4*)&sC[st][t][ln * 8];
            float4 c1 = *(float4*)&sC[st][t][ln * 8 + 4];
            S[0] = fmaf(S[0], a, dtx * b0.x);
            S[1] = fmaf(S[1], a, dtx * b0.y);
            S[2] = fmaf(S[2], a, dtx * b0.z);
            S[3] = fmaf(S[3], a, dtx * b0.w);
            S[4] = fmaf(S[4], a, dtx * b1.x);
            S[5] = fmaf(S[5], a, dtx * b1.y);
            S[6] = fmaf(S[6], a, dtx * b1.z);
            S[7] = fmaf(S[7], a, dtx * b1.w);
            float part = S[0] * c0.x;
            part = fmaf(S[1], c0.y, part);
            part = fmaf(S[2], c0.z, part);
            part = fmaf(S[3], c0.w, part);
            part = fmaf(S[4], c1.x, part);
            part = fmaf(S[5], c1.y, part);
            part = fmaf(S[6], c1.z, part);
            part = fmaf(S[7], c1.w, part);
            part += __shfl_down_sync(0xffffffffu, part, 4, 8);
            part += __shfl_down_sync(0xffffffffu, part, 2, 8);
            part += __shfl_down_sync(0xffffffffu, part, 1, 8);
            if (ln == 0) yp[gbase + (size_t)t * DIN] = part;
            if (doprod) prodb[prbase + (size_t)c * SC_T + t] = pa;
        }
    }
    size_t so = (size_t)blockIdx.x * 4096 + (size_t)tid * 8;
#pragma unroll
    for (int j = 0; j < 8; j += 4)
        *(float4*)&Send[so + j] = make_float4(S[j], S[j + 1], S[j + 2], S[j + 3]);
}

// ---------------- Phase 2: combine chunk states -> S_start per chunk ----------------
__global__ void scan_p2_kernel(const float* __restrict__ Send, const float* __restrict__ prodb,
                               float* __restrict__ Sstart) {
    int s = blockIdx.x & 1, h = (blockIdx.x >> 1) & 31, b = blockIdx.x >> 6;
    int tid = threadIdx.x;
    int base_bid = ((b * NH + h) * 2 + s) * CKN;
    size_t prbase = (size_t)(b * NH + h) * LL;
    float acc[8];
#pragma unroll
    for (int j = 0; j < 8; j++) acc[j] = 0.f;
    for (int ck = 0; ck < CKN; ck++) {
        size_t o = (size_t)(base_bid + ck) * 4096 + (size_t)tid * 8;
        *(float4*)&Sstart[o] = make_float4(acc[0], acc[1], acc[2], acc[3]);
        *(float4*)&Sstart[o + 4] = make_float4(acc[4], acc[5], acc[6], acc[7]);
        float pc = prodb[prbase + (size_t)ck * CKL + (CKL - 1)];
        float4 e0 = *(const float4*)&Send[o];
        float4 e1 = *(const float4*)&Send[o + 4];
        acc[0] = fmaf(acc[0], pc, e0.x);
        acc[1] = fmaf(acc[1], pc, e0.y);
        acc[2] = fmaf(acc[2], pc, e0.z);
        acc[3] = fmaf(acc[3], pc, e0.w);
        acc[4] = fmaf(acc[4], pc, e1.x);
        acc[5] = fmaf(acc[5], pc, e1.y);
        acc[6] = fmaf(acc[6], pc, e1.z);
        acc[7] = fmaf(acc[7], pc, e1.w);
    }
}

// ---------------- Phase 3: y += prod_t * (C_t . S_start), 256-step tiles ----------------
#define P3_CPAD 68
#define P3_SMEMF (64 * P3_CPAD + 256 * P3_CPAD + 256)
#define P3_SMEMB (P3_SMEMF * 4)

__global__ __launch_bounds__(512, 1) void scan_p3_kernel(const float* __restrict__ conv,
                                                         const float* __restrict__ Sstart,
                                                         const float* __restrict__ prodb,
                                                         float* __restrict__ yp0,
                                                         float* __restrict__ yp1) {
    const int tile = blockIdx.x & 15;
    const int t0 = tile * 256;
    const int ck = t0 / CKL;           // CKL = 512 -> ck = tile >> 1
    if (ck == 0) return;
    const int s = (blockIdx.x >> 4) & 1;
    const int h = (blockIdx.x >> 5) & 31;
    const int b = blockIdx.x >> 10;
    float* __restrict__ yp = s ? yp1 : yp0;
    const int n0 = s * 64;
    const int tid = threadIdx.x;

    extern __shared__ float p3s[];
    float* Ss = p3s;                      // [64][P3_CPAD]
    float* Cs = p3s + 64 * P3_CPAD;       // [256][P3_CPAD]
    float* pr = Cs + 256 * P3_CPAD;       // [256]

    // load S_start for this chunk
    size_t ssb = ((size_t)(((b * NH + h) * 2 + s) * CKN + ck)) * 4096;
    for (int q = tid; q < 1024; q += 512) {
        int row = q >> 4, quad = q & 15;
        float4 v = *(const float4*)&Sstart[ssb + (size_t)row * 64 + quad * 4];
        *(float4*)&Ss[row * P3_CPAD + quad * 4] = v;
    }
    // load prod (cumulative within chunk; tile offset toff into chunk)
    int toff = t0 - ck * CKL;
    size_t prb = (size_t)(b * NH + h) * LL + (size_t)ck * CKL + toff;
    if (tid < 256) pr[tid] = prodb[prb + tid];
    // load C rows
    size_t t0row = (size_t)b * LL + t0;
    for (int q = tid; q < 4096; q += 512) {
        int tt = q >> 4, quad = q & 15;
        float4 v = *(const float4*)(conv + (t0row + tt) * CONVDIM + 2176 + n0 + quad * 4);
        *(float4*)&Cs[tt * P3_CPAD + quad * 4] = v;
    }
    __syncthreads();

    const int tg = tid >> 3;
    const int pp = tid & 7;
    float acc[4][8];
#pragma unroll
    for (int i = 0; i < 4; i++)
#pragma unroll
        for (int k = 0; k < 8; k++) acc[i][k] = 0.f;

#pragma unroll
    for (int quad = 0; quad < 16; quad++) {
        float4 cv[4], sv[8];
#pragma unroll
        for (int i = 0; i < 4; i++) cv[i] = *(float4*)&Cs[(tg * 4 + i) * P3_CPAD + quad * 4];
#pragma unroll
        for (int k = 0; k < 8; k++) sv[k] = *(float4*)&Ss[(pp * 8 + k) * P3_CPAD + quad * 4];
#pragma unroll
        for (int i = 0; i < 4; i++)
#pragma unroll
            for (int k = 0; k < 8; k++) {
                acc[i][k] = fmaf(cv[i].x, sv[k].x, acc[i][k]);
                acc[i][k] = fmaf(cv[i].y, sv[k].y, acc[i][k]);
                acc[i][k] = fmaf(cv[i].z, sv[k].z, acc[i][k]);
                acc[i][k] = fmaf(cv[i].w, sv[k].w, acc[i][k]);
            }
    }

#pragma unroll
    for (int i = 0; i < 4; i++) {
        int tl = tg * 4 + i;
        float pt = pr[tl];
        size_t yo = ((size_t)b * LL + t0 + tl) * DIN + h * HD + pp * 8;
        float4 y0 = *(float4*)&yp[yo];
        float4 y1v = *(float4*)&yp[yo + 4];
        y0.x = fmaf(pt, acc[i][0], y0.x);
        y0.y = fmaf(pt, acc[i][1], y0.y);
        y0.z = fmaf(pt, acc[i][2], y0.z);
        y0.w = fmaf(pt, acc[i][3], y0.w);
        y1v.x = fmaf(pt, acc[i][4], y1v.x);
        y1v.y = fmaf(pt, acc[i][5], y1v.y);
        y1v.z = fmaf(pt, acc[i][6], y1v.z);
        y1v.w = fmaf(pt, acc[i][7], y1v.w);
        *(float4*)&yp[yo] = y0;
        *(float4*)&yp[yo + 4] = y1v;
    }
}

// ---------------- gated rmsnorm -> fp16 ----------------
__global__ void gnorm_h_kernel(const float* __restrict__ y1, const float* __restrict__ y2,
                               const float* __restrict__ conv, const float* __restrict__ Dp,
                               const float* __restrict__ zx, const float* __restrict__ gw,
                               __half* __restrict__ oh) {
    size_t row = blockIdx.x;
    const float* zr = zx + row * DPROJ;
    float v[8];
    float ss = 0.f;
#pragma unroll
    for (int u = 0; u < 8; u++) {
        int i = threadIdx.x + u * 256;
        float xv = conv[row * CONVDIM + i];
        float yv = y1[row * DIN + i] + y2[row * DIN + i] + Dp[i >> 6] * xv;
        float z = zr[i];
        float val = yv * siluf(z);
        v[u] = val;
        ss += val * val;
    }
    ss = blockReduceSum(ss);
    float inv = rsqrtf(ss / (float)DIN + 1e-5f);
#pragma unroll
    for (int u = 0; u < 8; u++) {
        int i = threadIdx.x + u * 256;
        oh[row * DIN + i] = __float2half(v[u] * inv * gw[i]);
    }
}

// ---------------- cumsum passes ----------------
__global__ void chunk_sum_kernel(const float* __restrict__ PQ, float* __restrict__ cs) {
    int c = (blockIdx.x & 3) * 256 + threadIdx.x;
    int chunk = (blockIdx.x >> 2) & (NCHUNK - 1);
    int b = blockIdx.x >> 5;
    float s = 0.f;
    size_t base = ((size_t)b * LL + (size_t)chunk * CHL) * (2 * DD) + DD + c;
    for (int l = 0; l < CHL; l++) s += PQ[base + (size_t)l * (2 * DD)];
    cs[((size_t)b * NCHUNK + chunk) * DD + c] = s;
}

__global__ void scan_chunks_kernel(float* __restrict__ cs) {
    int i = blockIdx.x * blockDim.x + threadIdx.x;
    if (i >= BB * DD) return;
    int b = i / DD, c = i % DD;
    float acc = 0.f;
#pragma unroll
    for (int ch = 0; ch < NCHUNK; ch++) {
        size_t o = ((size_t)b * NCHUNK + ch) * DD + c;
        float v = cs[o];
        cs[o] = acc;
        acc += v;
    }
}

__global__ void final_kernel(const float* __restrict__ x, const float* __restrict__ PQ,
                             const float* __restrict__ R,
                             const float* __restrict__ cs, float* __restrict__ out) {
    int c = (blockIdx.x & 3) * 256 + threadIdx.x;
    int chunk = (blockIdx.x >> 2) & (NCHUNK - 1);
    int b = blockIdx.x >> 5;
    float acc = cs[((size_t)b * NCHUNK + chunk) * DD + c];
    size_t rbase = ((size_t)b * LL + (size_t)chunk * CHL) * DD + c;
    size_t pqbase = ((size_t)b * LL + (size_t)chunk * CHL) * (2 * DD) + c;
    for (int l = 0; l < CHL; l++) {
        size_t idx = rbase + (size_t)l * DD;
        size_t pqi = pqbase + (size_t)l * (2 * DD);
        acc += PQ[pqi + DD];
        out[idx] = x[idx] + PQ[pqi] + R[idx] + acc;
    }
}

// ---------------- launch ----------------
extern "C" void kernel_launch(void* const* d_in, const int* in_sizes, int n_in,
                              void* d_out, int out_size) {
    const float* x       = (const float*)d_in[0];
    const float* norm_w  = (const float*)d_in[1];
    const float* in_proj = (const float*)d_in[2];
    const float* conv_W  = (const float*)d_in[3];
    const float* conv_b  = (const float*)d_in[4];
    const float* dt_bias = (const float*)d_in[5];
    const float* A_log   = (const float*)d_in[6];
    const float* Dvec    = (const float*)d_in[7];
    const float* gnorm_w = (const float*)d_in[8];
    const float* zero_W  = (const float*)d_in[9];
    const float* one_W   = (const float*)d_in[10];
    const float* fusion  = (const float*)d_in[11];
    float* out = (float*)d_out;

    float *zx, *conv, *dt, *dA, *y1, *y2, *PQ, *R, *Wz, *Wc, *cs, *Send, *Sstart, *prodb;
    __half *xnh, *Wpt, *Fzt, *Fot, *Fmt, *zw, *ow, *Wpq, *yh;
    cudaGetSymbolAddress((void**)&zx, g_zx);
    cudaGetSymbolAddress((void**)&conv, g_conv);
    cudaGetSymbolAddress((void**)&dt, g_dt);
    cudaGetSymbolAddress((void**)&dA, g_dA);
    cudaGetSymbolAddress((void**)&y1, g_y1);
    cudaGetSymbolAddress((void**)&y2, g_y2);
    cudaGetSymbolAddress((void**)&PQ, g_PQ);
    cudaGetSymbolAddress((void**)&R, g_R);
    cudaGetSymbolAddress((void**)&Wz, g_Wz);
    cudaGetSymbolAddress((void**)&Wc, g_Wc);
    cudaGetSymbolAddress((void**)&cs, g_cs);
    cudaGetSymbolAddress((void**)&Send, g_Send);
    cudaGetSymbolAddress((void**)&Sstart, g_Sstart);
    cudaGetSymbolAddress((void**)&prodb, g_prod);
    cudaGetSymbolAddress((void**)&xnh, g_xnh);
    cudaGetSymbolAddress((void**)&Wpt, g_Wpt);
    cudaGetSymbolAddress((void**)&Fzt, g_Fzt);
    cudaGetSymbolAddress((void**)&Fot, g_Fot);
    cudaGetSymbolAddress((void**)&Fmt, g_Fmt);
    cudaGetSymbolAddress((void**)&zw, g_zw);
    cudaGetSymbolAddress((void**)&ow, g_ow);
    cudaGetSymbolAddress((void**)&Wpq, g_Wpq);
    cudaGetSymbolAddress((void**)&yh, g_yh);

    const int M = BB * LL;
    cudaFuncSetAttribute(tgemm_kernel, cudaFuncAttributeMaxDynamicSharedMemorySize, TG_SMEM);
    cudaFuncSetAttribute(scan_p3_kernel, cudaFuncAttributeMaxDynamicSharedMemorySize, P3_SMEMB);

    cudaStream_t s2;
    cudaEvent_t ev0, evA, evB;
    cudaStreamCreateWithFlags(&s2, cudaStreamNonBlocking);
    cudaEventCreateWithFlags(&ev0, cudaEventDisableTiming);
    cudaEventCreateWithFlags(&evA, cudaEventDisableTiming);
    cudaEventCreateWithFlags(&evB, cudaEventDisableTiming);

    dim3 tb(32, 8);

    // ---- main: shared prep ----
    rmsnorm_h_kernel<<<M, 256>>>(x, norm_w, xnh);
    transpose_h_kernel<<<dim3(DD / 32, NPADPROJ / 32), tb>>>(in_proj, DD, DPROJ, Wpt, NPADPROJ);
    transpose_h_kernel<<<dim3(DIN / 32, DD / 32), tb>>>(fusion, DIN, DD, Fmt, DD);
    cudaEventRecord(ev0, 0);

    // ---- main: xBC+dt half of zx, conv, dtda ----
    tgemm_kernel<<<dim3((NPADPROJ - 2048) / 128, M / 128), 256, TG_SMEM>>>(xnh, Wpt, zx, M, DPROJ, DD, 2048);
    {
        size_t tot = (size_t)BB * LL * CONVDIM;
        conv_kernel<<<(unsigned)((tot + 255) / 256), 256>>>(zx, conv_W, conv_b, conv);
        size_t tot2 = (size_t)BB * LL * NH;
        dtda_kernel<<<(unsigned)((tot2 + 255) / 256), 256>>>(zx, dt_bias, A_log, dt, dA);
    }
    cudaEventRecord(evA, 0);

    // ---- side: z half of zx, then 3-phase scan -> gnorm -> R ----
    cudaStreamWaitEvent(s2, ev0, 0);
    tgemm_kernel<<<dim3(2048 / 128, M / 128), 256, TG_SMEM, s2>>>(xnh, Wpt, zx, M, DPROJ, DD, 0);
    cudaStreamWaitEvent(s2, evA, 0);
    scan_p1_kernel<<<NBLK1, 512, 0, s2>>>(conv, dt, dA, y1, y2, Send, prodb);
    scan_p2_kernel<<<128, 512, 0, s2>>>(Send, prodb, Sstart);
    scan_p3_kernel<<<NBLK3, 512, P3_SMEMB, s2>>>(conv, Sstart, prodb, y1, y2);
    gnorm_h_kernel<<<M, 256, 0, s2>>>(y1, y2, conv, Dvec, zx, gnorm_w, yh);
    tgemm_kernel<<<dim3(8, M / 128), 256, TG_SMEM, s2>>>(yh, Fmt, R, M, DD, DIN, 0);
    cudaEventRecord(evB, s2);

    // ---- main (concurrent): combines -> PQ -> cumsum prefix ----
    {
        size_t n = (size_t)DD * DIN;
        tohalf_kernel<<<(unsigned)((n + 255) / 256), 256>>>(zero_W, zw, n);
        tohalf_kernel<<<(unsigned)((n + 255) / 256), 256>>>(one_W, ow, n);
        transpose_h_kernel<<<dim3(DIN / 32, DD / 32), tb>>>(fusion + (size_t)DIN * DD, DIN, DD, Fzt, DD);
        transpose_h_kernel<<<dim3(DIN / 32, DD / 32), tb>>>(fusion + (size_t)2 * DIN * DD, DIN, DD, Fot, DD);
    }
    tgemm_kernel<<<dim3(8, 8), 256, TG_SMEM>>>(zw, Fzt, Wz, DD, DD, DIN, 0);
    tgemm_kernel<<<dim3(8, 8), 256, TG_SMEM>>>(ow, Fot, Wc, DD, DD, DIN, 0);
    transpose_h_kernel<<<dim3(DD / 32, DD / 32), tb>>>(Wz, DD, DD, Wpq, DD);
    transpose_h_kernel<<<dim3(DD / 32, DD / 32), tb>>>(Wc, DD, DD, Wpq + (size_t)DD * DD, DD);
    tgemm_kernel<<<dim3(16, M / 128), 256, TG_SMEM>>>(xnh, Wpq, PQ, M, 2 * DD, DD, 0);
    chunk_sum_kernel<<<BB * NCHUNK * 4, 256>>>(PQ, cs);
    scan_chunks_kernel<<<(BB * DD + 255) / 256, 256>>>(cs);

    // ---- join ----
    cudaStreamWaitEvent(0, evB, 0);
    final_kernel<<<BB * NCHUNK * 4, 256>>>(x, PQ, R, cs, out);

    cudaEventDestroy(ev0);
    cudaEventDestroy(evA);
    cudaEventDestroy(evB);
    cudaStreamDestroy(s2);
}

// round 16
// speedup vs baseline: 1.6824x; 1.6751x over previous
#include <cuda_runtime.h>
#include <cuda_bf16.h>
#include <cuda_fp16.h>
#include <math.h>
#include <stdint.h>

#define BB 2
#define LL 4096
#define DD 1024
#define DIN 2048
#define DSTATE 128
#define NH 32
#define HD 64
#define CONVDIM 2304
#define DPROJ 4384
#define NPADPROJ 4480
#define NCHUNK 8
#define CHL (LL / NCHUNK)

// SSD chunking
#define SSD_T 64
#define SSD_NCK (LL / SSD_T)          // 64 chunks
#define NSSD (BB * NH * SSD_NCK)      // 4096 blocks

// ---------------- scratch (device globals) ----------------
__device__ float g_zx[BB * LL * DPROJ];
__device__ float g_conv[BB * LL * CONVDIM];
__device__ float g_dt[BB * LL * NH];
__device__ float g_ld[BB * LL * NH];          // log dA
__device__ float g_y[BB * LL * DIN];
__device__ float g_PQ[BB * LL * 2 * DD];
__device__ float g_R[BB * LL * DD];
__device__ float g_Wz[DD * DD];
__device__ float g_Wc[DD * DD];
__device__ float g_cs[BB * NCHUNK * DD];
__device__ float g_Sd[(size_t)NSSD * 8192];   // S_delta per (b,h,ck): [64p][128n]
__device__ float g_Ss[(size_t)NSSD * 8192];   // S_start per (b,h,ck)
__device__ float g_Ac[NSSD];                  // chunk decay exp(L63)
__device__ float g_At[(size_t)NSSD * 64];     // exp(L_t) per (b,h,ck,t)

__device__ __half g_xnh[BB * LL * DD];
__device__ __half g_Wpt[NPADPROJ * DD];
__device__ __half g_Fzt[DD * DIN];
__device__ __half g_Fot[DD * DIN];
__device__ __half g_Fmt[DD * DIN];
__device__ __half g_zw[DD * DIN];
__device__ __half g_ow[DD * DIN];
__device__ __half g_Wpq[2 * DD * DD];
__device__ __half g_yh[BB * LL * DIN];

// ---------------- helpers ----------------
__device__ __forceinline__ uint32_t s2u(const void* p) {
    uint32_t a;
    asm("{ .reg .u64 t; cvta.to.shared.u64 t, %1; cvt.u32.u64 %0, t; }" : "=r"(a) : "l"(p));
    return a;
}

#define LDSM4(r0, r1, r2, r3, addr)                                                         \
    asm volatile("ldmatrix.sync.aligned.m8n8.x4.shared.b16 {%0,%1,%2,%3}, [%4];"            \
                 : "=r"(r0), "=r"(r1), "=r"(r2), "=r"(r3) : "r"(addr))

#define MMA16816H(c, a, b)                                                                  \
    asm volatile("mma.sync.aligned.m16n8k16.row.col.f32.f16.f16.f32 "                       \
                 "{%0,%1,%2,%3}, {%4,%5,%6,%7}, {%8,%9}, {%0,%1,%2,%3};"                    \
                 : "+f"((c)[0]), "+f"((c)[1]), "+f"((c)[2]), "+f"((c)[3])                   \
                 : "r"((a)[0]), "r"((a)[1]), "r"((a)[2]), "r"((a)[3]),                      \
                   "r"((b)[0]), "r"((b)[1]))

__inline__ __device__ float blockReduceSum(float v) {
    __shared__ float sh[32];
    int lane = threadIdx.x & 31, wid = threadIdx.x >> 5;
#pragma unroll
    for (int o = 16; o > 0; o >>= 1) v += __shfl_down_sync(0xffffffffu, v, o);
    if (lane == 0) sh[wid] = v;
    __syncthreads();
    v = (threadIdx.x < (blockDim.x >> 5)) ? sh[lane] : 0.f;
    if (wid == 0) {
#pragma unroll
        for (int o = 16; o > 0; o >>= 1) v += __shfl_down_sync(0xffffffffu, v, o);
        if (lane == 0) sh[0] = v;
    }
    __syncthreads();
    return sh[0];
}

__inline__ __device__ float siluf(float v) { return v / (1.f + expf(-v)); }

// ---------------- rmsnorm -> fp16 ----------------
__global__ void rmsnorm_h_kernel(const float* __restrict__ x, const float* __restrict__ w,
                                 __half* __restrict__ oh) {
    size_t row = blockIdx.x;
    const float* xr = x + row * DD;
    float ss = 0.f;
    for (int i = threadIdx.x; i < DD; i += blockDim.x) { float v = xr[i]; ss += v * v; }
    ss = blockReduceSum(ss);
    float inv = rsqrtf(ss / (float)DD + 1e-5f);
    for (int i = threadIdx.x; i < DD; i += blockDim.x)
        oh[row * DD + i] = __float2half(xr[i] * inv * w[i]);
}

// ---------------- transpose -> fp16 ----------------
__global__ void transpose_h_kernel(const float* __restrict__ src, int K, int N,
                                   __half* __restrict__ out, int Npad) {
    __shared__ float tile[32][33];
    int k0 = blockIdx.x * 32, n0 = blockIdx.y * 32;
#pragma unroll
    for (int i = 0; i < 4; i++) {
        int k = k0 + threadIdx.y + i * 8;
        int n = n0 + threadIdx.x;
        float v = (k < K && n < N) ? src[(size_t)k * N + n] : 0.f;
        tile[threadIdx.y + i * 8][threadIdx.x] = v;
    }
    __syncthreads();
#pragma unroll
    for (int i = 0; i < 4; i++) {
        int n = n0 + threadIdx.y + i * 8;
        int k = k0 + threadIdx.x;
        if (n < Npad && k < K)
            out[(size_t)n * K + k] = __float2half(tile[threadIdx.x][threadIdx.y + i * 8]);
    }
}

// ---------------- elementwise to fp16 ----------------
__global__ void tohalf_kernel(const float* __restrict__ src, __half* __restrict__ oh, size_t n) {
    size_t i = (size_t)blockIdx.x * blockDim.x + threadIdx.x;
    if (i >= n) return;
    oh[i] = __float2half(src[i]);
}

// ---------------- fp16 single-pass mma GEMM with column offset ----------------
#define TG_STAGE_BYTES 16384
#define TG_STAGES 4
#define TG_SMEM (TG_STAGES * TG_STAGE_BYTES)

__global__ __launch_bounds__(256, 2) void tgemm_kernel(const __half* __restrict__ A,
                                                       const __half* __restrict__ B,
                                                       float* __restrict__ C, int M, int N, int K,
                                                       int nbase) {
    extern __shared__ char smg[];
    uint32_t sb = s2u(smg);
    const int tid = threadIdx.x;
    const int wid = tid >> 5, lid = tid & 31;
    const int m0 = blockIdx.y * 128, n0 = blockIdx.x * 128 + nbase;
    const int wm = wid & 1, wn = wid >> 1;
    const int lr = lid & 15, lu = lid >> 4;
    const int NKC = K >> 5;

    const __half* gsrc[4];
    uint32_t dsto[4];
#pragma unroll
    for (int i = 0; i < 4; i++) {
        int q = tid + i * 256;
        int arr = q >> 9, idx = q & 511, row = idx >> 2, u = idx & 3;
        const __half* base = (arr == 0) ? A : B;
        int grow = ((arr == 0) ? m0 : n0) + row;
        gsrc[i] = base + (size_t)grow * K + u * 8;
        dsto[i] = (uint32_t)(arr * 8192 + row * 64 + ((u ^ (row & 3)) << 4));
    }

    auto issue = [&](int kc, int buf) {
        uint32_t sbuf = sb + buf * TG_STAGE_BYTES;
#pragma unroll
        for (int i = 0; i < 4; i++)
            asm volatile("cp.async.cg.shared.global [%0], [%1], 16;" ::
                         "r"(sbuf + dsto[i]), "l"((const void*)(gsrc[i] + (size_t)kc * 32))
                         : "memory");
    };

    float acc[4][4][4];
#pragma unroll
    for (int a = 0; a < 4; a++)
#pragma unroll
        for (int b = 0; b < 4; b++)
#pragma unroll
            for (int c = 0; c < 4; c++) acc[a][b][c] = 0.f;

    issue(0, 0);
    asm volatile("cp.async.commit_group;" ::: "memory");
    issue(1, 1);
    asm volatile("cp.async.commit_group;" ::: "memory");
    issue(2, 2);
    asm volatile("cp.async.commit_group;" ::: "memory");

    for (int kc = 0; kc < NKC; kc++) {
        asm volatile("cp.async.wait_group 2;" ::: "memory");
        __syncthreads();
        int nk = kc + 3;
        if (nk < NKC) issue(nk, nk & 3);
        asm volatile("cp.async.commit_group;" ::: "memory");

        uint32_t ab = sb + (kc & 3) * TG_STAGE_BYTES;
#pragma unroll
        for (int s = 0; s < 2; s++) {
            uint32_t af[4][4], bf[4][2];
#pragma unroll
            for (int mt = 0; mt < 4; mt++) {
                int r = wm * 64 + mt * 16 + lr;
                int u = 2 * s + lu;
                uint32_t ad = ab + r * 64 + ((u ^ (r & 3)) << 4);
                LDSM4(af[mt][0], af[mt][1], af[mt][2], af[mt][3], ad);
            }
#pragma unroll
            for (int p = 0; p < 2; p++) {
                int r = wn * 32 + p * 16 + lr;
                int u = 2 * s + lu;
                uint32_t bd = ab + 8192 + r * 64 + ((u ^ (r & 3)) << 4);
                uint32_t t0, t1, t2, t3;
                LDSM4(t0, t1, t2, t3, bd);
                bf[p * 2 + 0][0] = t0; bf[p * 2 + 0][1] = t2;
                bf[p * 2 + 1][0] = t1; bf[p * 2 + 1][1] = t3;
            }
#pragma unroll
            for (int mt = 0; mt < 4; mt++)
#pragma unroll
                for (int nt = 0; nt < 4; nt++)
                    MMA16816H(acc[mt][nt], af[mt], bf[nt]);
        }
    }

#pragma unroll
    for (int mt = 0; mt < 4; mt++) {
        int r = m0 + wm * 64 + mt * 16 + (lid >> 2);
#pragma unroll
        for (int nt = 0; nt < 4; nt++) {
            int n = n0 + wn * 32 + nt * 8 + (lid & 3) * 2;
            if (n < N) {
                *(float2*)&C[(size_t)r * N + n] = make_float2(acc[mt][nt][0], acc[mt][nt][1]);
                *(float2*)&C[(size_t)(r + 8) * N + n] = make_float2(acc[mt][nt][2], acc[mt][nt][3]);
            }
        }
    }
}

// ---------------- conv + silu ----------------
__global__ void conv_kernel(const float* __restrict__ zx, const float* __restrict__ cw,
                            const float* __restrict__ cb, float* __restrict__ out) {
    size_t idx = (size_t)blockIdx.x * blockDim.x + threadIdx.x;
    if (idx >= (size_t)BB * LL * CONVDIM) return;
    int c = idx % CONVDIM;
    size_t rest = idx / CONVDIM;
    int t = rest % LL;
    int b = rest / LL;
    float acc = cb[c];
#pragma unroll
    for (int k = 0; k < 4; k++) {
        int tt = t - 3 + k;
        if (tt >= 0)
            acc += zx[((size_t)b * LL + tt) * DPROJ + DIN + c] * cw[k * CONVDIM + c];
    }
    out[idx] = siluf(acc);
}

// ---------------- dt softplus + log dA ----------------
__global__ void dtda_kernel(const float* __restrict__ zx, const float* __restrict__ dtb,
                            const float* __restrict__ alog, float* __restrict__ dtO,
                            float* __restrict__ ldO) {
    size_t idx = (size_t)blockIdx.x * blockDim.x + threadIdx.x;
    if (idx >= (size_t)BB * LL * NH) return;
    int h = idx % NH;
    size_t row = idx / NH;
    float raw = zx[row * DPROJ + (DPROJ - NH) + h] + dtb[h];
    float sp = (raw > 20.f) ? raw : log1pf(expf(raw));
    dtO[idx] = sp;
    ldO[idx] = sp * (-expf(alog[h]));   // log(dA)
}

// ---------------- SSD phase A: per-chunk intra work ----------------
// grid NSSD=4096: ck=bid&63, h=(bid>>6)&31, b=bid>>11. 512 threads.
// Computes y_intra -> g_y, S_delta -> g_Sd, Ac, At.
#define SA_CP 132
#define SA_XP 68
#define SA_SMEMF (2 * 64 * SA_CP + 2 * 64 * SA_XP + 4 * 64)
#define SA_SMEMB (SA_SMEMF * 4)

__global__ __launch_bounds__(512) void ssd_a_kernel(const float* __restrict__ conv,
                                                    const float* __restrict__ dtp,
                                                    const float* __restrict__ ldp,
                                                    float* __restrict__ y,
                                                    float* __restrict__ Sd,
                                                    float* __restrict__ Ac,
                                                    float* __restrict__ Atg) {
    const int ck = blockIdx.x & 63;
    const int h = (blockIdx.x >> 6) & 31;
    const int b = blockIdx.x >> 11;
    const size_t t0r = (size_t)b * LL + (size_t)ck * SSD_T;
    const int tid = threadIdx.x;

    extern __shared__ float sa[];
    float* sC = sa;                        // [64][132]
    float* sB = sC + 64 * SA_CP;           // [64][132]
    float* sXT = sB + 64 * SA_CP;          // [64p][68u]
    float* sG = sXT + 64 * SA_XP;          // [64t][68u]
    float* sL = sG + 64 * SA_XP;           // [64]
    float* sdt = sL + 64;
    float* swv = sdt + 64;                 // raw ldA then wv
    float* sAt = swv + 64;

    // loads: C and B rows (128 floats each)
    for (int q = tid; q < 2048; q += 512) {
        int row = q >> 5, quad = q & 31;
        const float* rowp = conv + (t0r + row) * CONVDIM;
        *(float4*)&sC[row * SA_CP + quad * 4] = *(const float4*)(rowp + 2176 + quad * 4);
        *(float4*)&sB[row * SA_CP + quad * 4] = *(const float4*)(rowp + 2048 + quad * 4);
    }
    // x transposed: sXT[p][u]
    for (int q = tid; q < 1024; q += 512) {
        int u = q >> 4, quad = q & 15;
        float4 v = *(const float4*)(conv + (t0r + u) * CONVDIM + h * HD + quad * 4);
        sXT[(quad * 4 + 0) * SA_XP + u] = v.x;
        sXT[(quad * 4 + 1) * SA_XP + u] = v.y;
        sXT[(quad * 4 + 2) * SA_XP + u] = v.z;
        sXT[(quad * 4 + 3) * SA_XP + u] = v.w;
    }
    if (tid < 64) {
        sdt[tid] = dtp[(t0r + tid) * NH + h];
        swv[tid] = ldp[(t0r + tid) * NH + h];
    }
    __syncthreads();
    // L prefix (inclusive)
    if (tid < 64) {
        float a = 0.f;
        for (int u = 0; u <= tid; u++) a += swv[u];
        sL[tid] = a;
    }
    __syncthreads();
    if (tid < 64) {
        float l63 = sL[63];
        sAt[tid] = expf(sL[tid]);
        float wv = expf(l63 - sL[tid]) * sdt[tid];
        swv[tid] = wv;
    }
    __syncthreads();

    // G = C @ B^T, masked -> sG[t][u]
    {
        const int tg = tid >> 5, ug = tid & 31;
        float acc[4][2];
#pragma unroll
        for (int i = 0; i < 4; i++) { acc[i][0] = 0.f; acc[i][1] = 0.f; }
#pragma unroll 8
        for (int q = 0; q < 32; q++) {
            float4 cv[4], bv[2];
#pragma unroll
            for (int i = 0; i < 4; i++) cv[i] = *(float4*)&sC[(tg * 4 + i) * SA_CP + q * 4];
#pragma unroll
            for (int j = 0; j < 2; j++) bv[j] = *(float4*)&sB[(ug * 2 + j) * SA_CP + q * 4];
#pragma unroll
            for (int i = 0; i < 4; i++)
#pragma unroll
                for (int j = 0; j < 2; j++) {
                    acc[i][j] = fmaf(cv[i].x, bv[j].x, acc[i][j]);
                    acc[i][j] = fmaf(cv[i].y, bv[j].y, acc[i][j]);
                    acc[i][j] = fmaf(cv[i].z, bv[j].z, acc[i][j]);
                    acc[i][j] = fmaf(cv[i].w, bv[j].w, acc[i][j]);
                }
        }
#pragma unroll
        for (int i = 0; i < 4; i++)
#pragma unroll
            for (int j = 0; j < 2; j++) {
                int t = tg * 4 + i, u = ug * 2 + j;
                float w = (u <= t) ? expf(sL[t] - sL[u]) * sdt[u] * acc[i][j] : 0.f;
                sG[t * SA_XP + u] = w;
            }
    }
    __syncthreads();

    // Y_intra = sG @ X  (y[t][p] = sum_u G[t][u] * XT[p][u])
    {
        const int tg = tid >> 5, pg = tid & 31;
        float acc[4][2];
#pragma unroll
        for (int i = 0; i < 4; i++) { acc[i][0] = 0.f; acc[i][1] = 0.f; }
#pragma unroll 4
        for (int q = 0; q < 16; q++) {
            float4 gv[4], xv[2];
#pragma unroll
            for (int i = 0; i < 4; i++) gv[i] = *(float4*)&sG[(tg * 4 + i) * SA_XP + q * 4];
#pragma unroll
            for (int j = 0; j < 2; j++) xv[j] = *(float4*)&sXT[(pg * 2 + j) * SA_XP + q * 4];
#pragma unroll
            for (int i = 0; i < 4; i++)
#pragma unroll
                for (int j = 0; j < 2; j++) {
                    acc[i][j] = fmaf(gv[i].x, xv[j].x, acc[i][j]);
                    acc[i][j] = fmaf(gv[i].y, xv[j].y, acc[i][j]);
                    acc[i][j] = fmaf(gv[i].z, xv[j].z, acc[i][j]);
                    acc[i][j] = fmaf(gv[i].w, xv[j].w, acc[i][j]);
                }
        }
#pragma unroll
        for (int i = 0; i < 4; i++) {
            int t = tg * 4 + i;
            size_t yo = (t0r + t) * DIN + h * HD + pg * 2;
            *(float2*)&y[yo] = make_float2(acc[i][0], acc[i][1]);
        }
    }
    __syncthreads();
    // scale XT by wv
    for (int q = tid; q < 4096; q += 512) {
        int p = q >> 6, u = q & 63;
        sXT[p * SA_XP + u] *= swv[u];
    }
    __syncthreads();
    // S_delta[p][n] = sum_u XT[p][u] * B[u][n]
    {
        const int pg = tid >> 5, ng = tid & 31;
        float acc[4][4];
#pragma unroll
        for (int i = 0; i < 4; i++)
#pragma unroll
            for (int j = 0; j < 4; j++) acc[i][j] = 0.f;
#pragma unroll 4
        for (int q = 0; q < 16; q++) {
            float4 xv[4], bv[4];
#pragma unroll
            for (int i = 0; i < 4; i++) xv[i] = *(float4*)&sXT[(pg * 4 + i) * SA_XP + q * 4];
#pragma unroll
            for (int r = 0; r < 4; r++) bv[r] = *(float4*)&sB[(q * 4 + r) * SA_CP + ng * 4];
#pragma unroll
            for (int i = 0; i < 4; i++)
#pragma unroll
                for (int j = 0; j < 4; j++) {
                    float bj0 = (&bv[0].x)[j], bj1 = (&bv[1].x)[j], bj2 = (&bv[2].x)[j], bj3 = (&bv[3].x)[j];
                    acc[i][j] = fmaf(xv[i].x, bj0, acc[i][j]);
                    acc[i][j] = fmaf(xv[i].y, bj1, acc[i][j]);
                    acc[i][j] = fmaf(xv[i].z, bj2, acc[i][j]);
                    acc[i][j] = fmaf(xv[i].w, bj3, acc[i][j]);
                }
        }
        size_t sdb = (size_t)blockIdx.x * 8192;
#pragma unroll
        for (int i = 0; i < 4; i++)
            *(float4*)&Sd[sdb + (size_t)(pg * 4 + i) * 128 + ng * 4] =
                make_float4(acc[i][0], acc[i][1], acc[i][2], acc[i][3]);
    }
    if (tid == 0) Ac[blockIdx.x] = expf(sL[63]);
    if (tid < 64) Atg[(size_t)blockIdx.x * 64 + tid] = sAt[tid];
}

// ---------------- SSD phase B: sequential chunk-state combine ----------------
// grid 64 (bh), 512 threads, 16 floats each.
__global__ void ssd_b_kernel(const float* __restrict__ Sd, const float* __restrict__ Ac,
                             float* __restrict__ Ss) {
    const int bh = blockIdx.x;
    const int tid = threadIdx.x;
    float S[16];
#pragma unroll
    for (int j = 0; j < 16; j++) S[j] = 0.f;
    for (int ck = 0; ck < SSD_NCK; ck++) {
        size_t g = (size_t)(bh * SSD_NCK + ck) * 8192 + (size_t)tid * 16;
#pragma unroll
        for (int j = 0; j < 16; j += 4)
            *(float4*)&Ss[g + j] = make_float4(S[j], S[j + 1], S[j + 2], S[j + 3]);
        float a = Ac[bh * SSD_NCK + ck];
#pragma unroll
        for (int j = 0; j < 16; j += 4) {
            float4 d = *(const float4*)&Sd[g + j];
            S[j + 0] = fmaf(S[j + 0], a, d.x);
            S[j + 1] = fmaf(S[j + 1], a, d.y);
            S[j + 2] = fmaf(S[j + 2], a, d.z);
            S[j + 3] = fmaf(S[j + 3], a, d.w);
        }
    }
}

// ---------------- SSD phase C: y += diag(At) * (C @ S_start) ----------------
#define SCC_SMEMF (2 * 64 * SA_CP + 64)
#define SCC_SMEMB (SCC_SMEMF * 4)

__global__ __launch_bounds__(512) void ssd_c_kernel(const float* __restrict__ conv,
                                                    const float* __restrict__ Ss,
                                                    const float* __restrict__ Atg,
                                                    float* __restrict__ y) {
    const int ck = blockIdx.x & 63;
    if (ck == 0) return;
    const int h = (blockIdx.x >> 6) & 31;
    const int b = blockIdx.x >> 11;
    const size_t t0r = (size_t)b * LL + (size_t)ck * SSD_T;
    const int tid = threadIdx.x;

    extern __shared__ float sc[];
    float* sC = sc;                       // [64t][132n]
    float* sS = sC + 64 * SA_CP;          // [64p][132n]
    float* sAt = sS + 64 * SA_CP;         // [64]

    for (int q = tid; q < 2048; q += 512) {
        int row = q >> 5, quad = q & 31;
        *(float4*)&sC[row * SA_CP + quad * 4] =
            *(const float4*)(conv + (t0r + row) * CONVDIM + 2176 + quad * 4);
        *(float4*)&sS[row * SA_CP + quad * 4] =
            *(const float4*)&Ss[(size_t)blockIdx.x * 8192 + (size_t)row * 128 + quad * 4];
    }
    if (tid < 64) sAt[tid] = Atg[(size_t)blockIdx.x * 64 + tid];
    __syncthreads();

    const int tg = tid >> 5, pg = tid & 31;
    float acc[4][2];
#pragma unroll
    for (int i = 0; i < 4; i++) { acc[i][0] = 0.f; acc[i][1] = 0.f; }
#pragma unroll 8
    for (int q = 0; q < 32; q++) {
        float4 cv[4], sv[2];
#pragma unroll
        for (int i = 0; i < 4; i++) cv[i] = *(float4*)&sC[(tg * 4 + i) * SA_CP + q * 4];
#pragma unroll
        for (int j = 0; j < 2; j++) sv[j] = *(float4*)&sS[(pg * 2 + j) * SA_CP + q * 4];
#pragma unroll
        for (int i = 0; i < 4; i++)
#pragma unroll
            for (int j = 0; j < 2; j++) {
                acc[i][j] = fmaf(cv[i].x, sv[j].x, acc[i][j]);
                acc[i][j] = fmaf(cv[i].y, sv[j].y, acc[i][j]);
                acc[i][j] = fmaf(cv[i].z, sv[j].z, acc[i][j]);
                acc[i][j] = fmaf(cv[i].w, sv[j].w, acc[i][j]);
            }
    }
#pragma unroll
    for (int i = 0; i < 4; i++) {
        int t = tg * 4 + i;
        float at = sAt[t];
        size_t yo = (t0r + t) * DIN + h * HD + pg * 2;
        float2 yv = *(float2*)&y[yo];
        yv.x = fmaf(at, acc[i][0], yv.x);
        yv.y = fmaf(at, acc[i][1], yv.y);
        *(float2*)&y[yo] = yv;
    }
}

// ---------------- gated rmsnorm (adds D*x) -> fp16 ----------------
__global__ void gnorm_h_kernel(const float* __restrict__ y,
                               const float* __restrict__ conv, const float* __restrict__ Dp,
                               const float* __restrict__ zx, const float* __restrict__ gw,
                               __half* __restrict__ oh) {
    size_t row = blockIdx.x;
    const float* zr = zx + row * DPROJ;
    float v[8];
    float ss = 0.f;
#pragma unroll
    for (int u = 0; u < 8; u++) {
        int i = threadIdx.x + u * 256;
        float xv = conv[row * CONVDIM + i];
        float yv = y[row * DIN + i] + Dp[i >> 6] * xv;
        float z = zr[i];
        float val = yv * siluf(z);
        v[u] = val;
        ss += val * val;
    }
    ss = blockReduceSum(ss);
    float inv = rsqrtf(ss / (float)DIN + 1e-5f);
#pragma unroll
    for (int u = 0; u < 8; u++) {
        int i = threadIdx.x + u * 256;
        oh[row * DIN + i] = __float2half(v[u] * inv * gw[i]);
    }
}

// ---------------- cumsum passes ----------------
__global__ void chunk_sum_kernel(const float* __restrict__ PQ, float* __restrict__ cs) {
    int c = (blockIdx.x & 3) * 256 + threadIdx.x;
    int chunk = (blockIdx.x >> 2) & (NCHUNK - 1);
    int b = blockIdx.x >> 5;
    float s = 0.f;
    size_t base = ((size_t)b * LL + (size_t)chunk * CHL) * (2 * DD) + DD + c;
    for (int l = 0; l < CHL; l++) s += PQ[base + (size_t)l * (2 * DD)];
    cs[((size_t)b * NCHUNK + chunk) * DD + c] = s;
}

__global__ void scan_chunks_kernel(float* __restrict__ cs) {
    int i = blockIdx.x * blockDim.x + threadIdx.x;
    if (i >= BB * DD) return;
    int b = i / DD, c = i % DD;
    float acc = 0.f;
#pragma unroll
    for (int ch = 0; ch < NCHUNK; ch++) {
        size_t o = ((size_t)b * NCHUNK + ch) * DD + c;
        float v = cs[o];
        cs[o] = acc;
        acc += v;
    }
}

__global__ void final_kernel(const float* __restrict__ x, const float* __restrict__ PQ,
                             const float* __restrict__ R,
                             const float* __restrict__ cs, float* __restrict__ out) {
    int c = (blockIdx.x & 3) * 256 + threadIdx.x;
    int chunk = (blockIdx.x >> 2) & (NCHUNK - 1);
    int b = blockIdx.x >> 5;
    float acc = cs[((size_t)b * NCHUNK + chunk) * DD + c];
    size_t rbase = ((size_t)b * LL + (size_t)chunk * CHL) * DD + c;
    size_t pqbase = ((size_t)b * LL + (size_t)chunk * CHL) * (2 * DD) + c;
    for (int l = 0; l < CHL; l++) {
        size_t idx = rbase + (size_t)l * DD;
        size_t pqi = pqbase + (size_t)l * (2 * DD);
        acc += PQ[pqi + DD];
        out[idx] = x[idx] + PQ[pqi] + R[idx] + acc;
    }
}

// ---------------- launch ----------------
extern "C" void kernel_launch(void* const* d_in, const int* in_sizes, int n_in,
                              void* d_out, int out_size) {
    const float* x       = (const float*)d_in[0];
    const float* norm_w  = (const float*)d_in[1];
    const float* in_proj = (const float*)d_in[2];
    const float* conv_W  = (const float*)d_in[3];
    const float* conv_b  = (const float*)d_in[4];
    const float* dt_bias = (const float*)d_in[5];
    const float* A_log   = (const float*)d_in[6];
    const float* Dvec    = (const float*)d_in[7];
    const float* gnorm_w = (const float*)d_in[8];
    const float* zero_W  = (const float*)d_in[9];
    const float* one_W   = (const float*)d_in[10];
    const float* fusion  = (const float*)d_in[11];
    float* out = (float*)d_out;

    float *zx, *conv, *dt, *ld, *y, *PQ, *R, *Wz, *Wc, *cs, *Sd, *Ss, *Ac, *At;
    __half *xnh, *Wpt, *Fzt, *Fot, *Fmt, *zw, *ow, *Wpq, *yh;
    cudaGetSymbolAddress((void**)&zx, g_zx);
    cudaGetSymbolAddress((void**)&conv, g_conv);
    cudaGetSymbolAddress((void**)&dt, g_dt);
    cudaGetSymbolAddress((void**)&ld, g_ld);
    cudaGetSymbolAddress((void**)&y, g_y);
    cudaGetSymbolAddress((void**)&PQ, g_PQ);
    cudaGetSymbolAddress((void**)&R, g_R);
    cudaGetSymbolAddress((void**)&Wz, g_Wz);
    cudaGetSymbolAddress((void**)&Wc, g_Wc);
    cudaGetSymbolAddress((void**)&cs, g_cs);
    cudaGetSymbolAddress((void**)&Sd, g_Sd);
    cudaGetSymbolAddress((void**)&Ss, g_Ss);
    cudaGetSymbolAddress((void**)&Ac, g_Ac);
    cudaGetSymbolAddress((void**)&At, g_At);
    cudaGetSymbolAddress((void**)&xnh, g_xnh);
    cudaGetSymbolAddress((void**)&Wpt, g_Wpt);
    cudaGetSymbolAddress((void**)&Fzt, g_Fzt);
    cudaGetSymbolAddress((void**)&Fot, g_Fot);
    cudaGetSymbolAddress((void**)&Fmt, g_Fmt);
    cudaGetSymbolAddress((void**)&zw, g_zw);
    cudaGetSymbolAddress((void**)&ow, g_ow);
    cudaGetSymbolAddress((void**)&Wpq, g_Wpq);
    cudaGetSymbolAddress((void**)&yh, g_yh);

    const int M = BB * LL;
    cudaFuncSetAttribute(tgemm_kernel, cudaFuncAttributeMaxDynamicSharedMemorySize, TG_SMEM);
    cudaFuncSetAttribute(ssd_a_kernel, cudaFuncAttributeMaxDynamicSharedMemorySize, SA_SMEMB);
    cudaFuncSetAttribute(ssd_c_kernel, cudaFuncAttributeMaxDynamicSharedMemorySize, SCC_SMEMB);

    cudaStream_t s2;
    cudaEvent_t ev0, evA, evB;
    cudaStreamCreateWithFlags(&s2, cudaStreamNonBlocking);
    cudaEventCreateWithFlags(&ev0, cudaEventDisableTiming);
    cudaEventCreateWithFlags(&evA, cudaEventDisableTiming);
    cudaEventCreateWithFlags(&evB, cudaEventDisableTiming);

    dim3 tb(32, 8);

    // ---- main: shared prep ----
    rmsnorm_h_kernel<<<M, 256>>>(x, norm_w, xnh);
    transpose_h_kernel<<<dim3(DD / 32, NPADPROJ / 32), tb>>>(in_proj, DD, DPROJ, Wpt, NPADPROJ);
    transpose_h_kernel<<<dim3(DIN / 32, DD / 32), tb>>>(fusion, DIN, DD, Fmt, DD);
    cudaEventRecord(ev0, 0);

    // ---- main: xBC+dt half of zx, conv, dt/ld ----
    tgemm_kernel<<<dim3((NPADPROJ - 2048) / 128, M / 128), 256, TG_SMEM>>>(xnh, Wpt, zx, M, DPROJ, DD, 2048);
    {
        size_t tot = (size_t)BB * LL * CONVDIM;
        conv_kernel<<<(unsigned)((tot + 255) / 256), 256>>>(zx, conv_W, conv_b, conv);
        size_t tot2 = (size_t)BB * LL * NH;
        dtda_kernel<<<(unsigned)((tot2 + 255) / 256), 256>>>(zx, dt_bias, A_log, dt, ld);
    }
    cudaEventRecord(evA, 0);

    // ---- side: z half of zx, then SSD scan -> gnorm -> R ----
    cudaStreamWaitEvent(s2, ev0, 0);
    tgemm_kernel<<<dim3(2048 / 128, M / 128), 256, TG_SMEM, s2>>>(xnh, Wpt, zx, M, DPROJ, DD, 0);
    cudaStreamWaitEvent(s2, evA, 0);
    ssd_a_kernel<<<NSSD, 512, SA_SMEMB, s2>>>(conv, dt, ld, y, Sd, Ac, At);
    ssd_b_kernel<<<BB * NH, 512, 0, s2>>>(Sd, Ac, Ss);
    ssd_c_kernel<<<NSSD, 512, SCC_SMEMB, s2>>>(conv, Ss, At, y);
    gnorm_h_kernel<<<M, 256, 0, s2>>>(y, conv, Dvec, zx, gnorm_w, yh);
    tgemm_kernel<<<dim3(8, M / 128), 256, TG_SMEM, s2>>>(yh, Fmt, R, M, DD, DIN, 0);
    cudaEventRecord(evB, s2);

    // ---- main (concurrent): combines -> PQ -> cumsum prefix ----
    {
        size_t n = (size_t)DD * DIN;
        tohalf_kernel<<<(unsigned)((n + 255) / 256), 256>>>(zero_W, zw, n);
        tohalf_kernel<<<(unsigned)((n + 255) / 256), 256>>>(one_W, ow, n);
        transpose_h_kernel<<<dim3(DIN / 32, DD / 32), tb>>>(fusion + (size_t)DIN * DD, DIN, DD, Fzt, DD);
        transpose_h_kernel<<<dim3(DIN / 32, DD / 32), tb>>>(fusion + (size_t)2 * DIN * DD, DIN, DD, Fot, DD);
    }
    tgemm_kernel<<<dim3(8, 8), 256, TG_SMEM>>>(zw, Fzt, Wz, DD, DD, DIN, 0);
    tgemm_kernel<<<dim3(8, 8), 256, TG_SMEM>>>(ow, Fot, Wc, DD, DD, DIN, 0);
    transpose_h_kernel<<<dim3(DD / 32, DD / 32), tb>>>(Wz, DD, DD, Wpq, DD);
    transpose_h_kernel<<<dim3(DD / 32, DD / 32), tb>>>(Wc, DD, DD, Wpq + (size_t)DD * DD, DD);
    tgemm_kernel<<<dim3(16, M / 128), 256, TG_SMEM>>>(xnh, Wpq, PQ, M, 2 * DD, DD, 0);
    chunk_sum_kernel<<<BB * NCHUNK * 4, 256>>>(PQ, cs);
    scan_chunks_kernel<<<(BB * DD + 255) / 256, 256>>>(cs);

    // ---- join ----
    cudaStreamWaitEvent(0, evB, 0);
    final_kernel<<<BB * NCHUNK * 4, 256>>>(x, PQ, R, cs, out);

    cudaEventDestroy(ev0);
    cudaEventDestroy(evA);
    cudaEventDestroy(evB);
    cudaStreamDestroy(s2);
}

// round 17
// speedup vs baseline: 1.8872x; 1.1218x over previous
#include <cuda_runtime.h>
#include <cuda_bf16.h>
#include <cuda_fp16.h>
#include <math.h>
#include <stdint.h>

#define BB 2
#define LL 4096
#define DD 1024
#define DIN 2048
#define DSTATE 128
#define NH 32
#define HD 64
#define CONVDIM 2304
#define DPROJ 4384
#define NPADPROJ 4480
#define NCHUNK 8
#define CHL (LL / NCHUNK)

// SSD chunking
#define SSD_T 64
#define SSD_NCK (LL / SSD_T)
#define NSSD (BB * NH * SSD_NCK)

// ---------------- scratch (device globals) ----------------
__device__ float g_zx[BB * LL * DPROJ];
__device__ float g_conv[BB * LL * CONVDIM];
__device__ float g_dt[BB * LL * NH];
__device__ float g_ld[BB * LL * NH];
__device__ float g_y[BB * LL * DIN];
__device__ float g_PQ[BB * LL * 2 * DD];
__device__ float g_R[BB * LL * DD];
__device__ float g_Wz[DD * DD];
__device__ float g_Wc[DD * DD];
__device__ float g_cs[BB * NCHUNK * DD];
__device__ float g_Sd[(size_t)NSSD * 8192];
__device__ float g_Ss[(size_t)NSSD * 8192];
__device__ float g_Ac[NSSD];
__device__ float g_At[(size_t)NSSD * 64];

__device__ __half g_xnh[BB * LL * DD];
__device__ __half g_Wpt[NPADPROJ * DD];
__device__ __half g_Fzt[DD * DIN];
__device__ __half g_Fot[DD * DIN];
__device__ __half g_Fmt[DD * DIN];
__device__ __half g_zw[DD * DIN];
__device__ __half g_ow[DD * DIN];
__device__ __half g_Wpq[2 * DD * DD];
__device__ __half g_yh[BB * LL * DIN];

// ---------------- helpers ----------------
__device__ __forceinline__ uint32_t s2u(const void* p) {
    uint32_t a;
    asm("{ .reg .u64 t; cvta.to.shared.u64 t, %1; cvt.u32.u64 %0, t; }" : "=r"(a) : "l"(p));
    return a;
}

#define LDSM4(r0, r1, r2, r3, addr)                                                         \
    asm volatile("ldmatrix.sync.aligned.m8n8.x4.shared.b16 {%0,%1,%2,%3}, [%4];"            \
                 : "=r"(r0), "=r"(r1), "=r"(r2), "=r"(r3) : "r"(addr))

#define MMA16816H(c, a, b)                                                                  \
    asm volatile("mma.sync.aligned.m16n8k16.row.col.f32.f16.f16.f32 "                       \
                 "{%0,%1,%2,%3}, {%4,%5,%6,%7}, {%8,%9}, {%0,%1,%2,%3};"                    \
                 : "+f"((c)[0]), "+f"((c)[1]), "+f"((c)[2]), "+f"((c)[3])                   \
                 : "r"((a)[0]), "r"((a)[1]), "r"((a)[2]), "r"((a)[3]),                      \
                   "r"((b)[0]), "r"((b)[1]))

// direct fragment loads from row-major [row][P] half smem (canonical m16n8k16 layout)
__device__ __forceinline__ void frag_ldA(uint32_t a[4], const __half* sm, int P, int r0, int k0, int lane) {
    int g = lane >> 2, th = lane & 3;
    a[0] = *(const uint32_t*)(sm + (r0 + g) * P + k0 + th * 2);
    a[1] = *(const uint32_t*)(sm + (r0 + g + 8) * P + k0 + th * 2);
    a[2] = *(const uint32_t*)(sm + (r0 + g) * P + k0 + 8 + th * 2);
    a[3] = *(const uint32_t*)(sm + (r0 + g + 8) * P + k0 + 8 + th * 2);
}
__device__ __forceinline__ void frag_ldB(uint32_t b[2], const __half* sm, int P, int c0, int k0, int lane) {
    int g = lane >> 2, th = lane & 3;
    b[0] = *(const uint32_t*)(sm + (c0 + g) * P + k0 + th * 2);
    b[1] = *(const uint32_t*)(sm + (c0 + g) * P + k0 + 8 + th * 2);
}

__inline__ __device__ float blockReduceSum(float v) {
    __shared__ float sh[32];
    int lane = threadIdx.x & 31, wid = threadIdx.x >> 5;
#pragma unroll
    for (int o = 16; o > 0; o >>= 1) v += __shfl_down_sync(0xffffffffu, v, o);
    if (lane == 0) sh[wid] = v;
    __syncthreads();
    v = (threadIdx.x < (blockDim.x >> 5)) ? sh[lane] : 0.f;
    if (wid == 0) {
#pragma unroll
        for (int o = 16; o > 0; o >>= 1) v += __shfl_down_sync(0xffffffffu, v, o);
        if (lane == 0) sh[0] = v;
    }
    __syncthreads();
    return sh[0];
}

__inline__ __device__ float siluf(float v) { return v / (1.f + expf(-v)); }

// ---------------- rmsnorm -> fp16 ----------------
__global__ void rmsnorm_h_kernel(const float* __restrict__ x, const float* __restrict__ w,
                                 __half* __restrict__ oh) {
    size_t row = blockIdx.x;
    const float* xr = x + row * DD;
    float ss = 0.f;
    for (int i = threadIdx.x; i < DD; i += blockDim.x) { float v = xr[i]; ss += v * v; }
    ss = blockReduceSum(ss);
    float inv = rsqrtf(ss / (float)DD + 1e-5f);
    for (int i = threadIdx.x; i < DD; i += blockDim.x)
        oh[row * DD + i] = __float2half(xr[i] * inv * w[i]);
}

// ---------------- transpose -> fp16 ----------------
__global__ void transpose_h_kernel(const float* __restrict__ src, int K, int N,
                                   __half* __restrict__ out, int Npad) {
    __shared__ float tile[32][33];
    int k0 = blockIdx.x * 32, n0 = blockIdx.y * 32;
#pragma unroll
    for (int i = 0; i < 4; i++) {
        int k = k0 + threadIdx.y + i * 8;
        int n = n0 + threadIdx.x;
        float v = (k < K && n < N) ? src[(size_t)k * N + n] : 0.f;
        tile[threadIdx.y + i * 8][threadIdx.x] = v;
    }
    __syncthreads();
#pragma unroll
    for (int i = 0; i < 4; i++) {
        int n = n0 + threadIdx.y + i * 8;
        int k = k0 + threadIdx.x;
        if (n < Npad && k < K)
            out[(size_t)n * K + k] = __float2half(tile[threadIdx.x][threadIdx.y + i * 8]);
    }
}

// ---------------- elementwise to fp16 ----------------
__global__ void tohalf_kernel(const float* __restrict__ src, __half* __restrict__ oh, size_t n) {
    size_t i = (size_t)blockIdx.x * blockDim.x + threadIdx.x;
    if (i >= n) return;
    oh[i] = __float2half(src[i]);
}

// ---------------- fp16 single-pass mma GEMM with column offset ----------------
#define TG_STAGE_BYTES 16384
#define TG_STAGES 4
#define TG_SMEM (TG_STAGES * TG_STAGE_BYTES)

__global__ __launch_bounds__(256, 2) void tgemm_kernel(const __half* __restrict__ A,
                                                       const __half* __restrict__ B,
                                                       float* __restrict__ C, int M, int N, int K,
                                                       int nbase) {
    extern __shared__ char smg[];
    uint32_t sb = s2u(smg);
    const int tid = threadIdx.x;
    const int wid = tid >> 5, lid = tid & 31;
    const int m0 = blockIdx.y * 128, n0 = blockIdx.x * 128 + nbase;
    const int wm = wid & 1, wn = wid >> 1;
    const int lr = lid & 15, lu = lid >> 4;
    const int NKC = K >> 5;

    const __half* gsrc[4];
    uint32_t dsto[4];
#pragma unroll
    for (int i = 0; i < 4; i++) {
        int q = tid + i * 256;
        int arr = q >> 9, idx = q & 511, row = idx >> 2, u = idx & 3;
        const __half* base = (arr == 0) ? A : B;
        int grow = ((arr == 0) ? m0 : n0) + row;
        gsrc[i] = base + (size_t)grow * K + u * 8;
        dsto[i] = (uint32_t)(arr * 8192 + row * 64 + ((u ^ (row & 3)) << 4));
    }

    auto issue = [&](int kc, int buf) {
        uint32_t sbuf = sb + buf * TG_STAGE_BYTES;
#pragma unroll
        for (int i = 0; i < 4; i++)
            asm volatile("cp.async.cg.shared.global [%0], [%1], 16;" ::
                         "r"(sbuf + dsto[i]), "l"((const void*)(gsrc[i] + (size_t)kc * 32))
                         : "memory");
    };

    float acc[4][4][4];
#pragma unroll
    for (int a = 0; a < 4; a++)
#pragma unroll
        for (int b = 0; b < 4; b++)
#pragma unroll
            for (int c = 0; c < 4; c++) acc[a][b][c] = 0.f;

    issue(0, 0);
    asm volatile("cp.async.commit_group;" ::: "memory");
    issue(1, 1);
    asm volatile("cp.async.commit_group;" ::: "memory");
    issue(2, 2);
    asm volatile("cp.async.commit_group;" ::: "memory");

    for (int kc = 0; kc < NKC; kc++) {
        asm volatile("cp.async.wait_group 2;" ::: "memory");
        __syncthreads();
        int nk = kc + 3;
        if (nk < NKC) issue(nk, nk & 3);
        asm volatile("cp.async.commit_group;" ::: "memory");

        uint32_t ab = sb + (kc & 3) * TG_STAGE_BYTES;
#pragma unroll
        for (int s = 0; s < 2; s++) {
            uint32_t af[4][4], bf[4][2];
#pragma unroll
            for (int mt = 0; mt < 4; mt++) {
                int r = wm * 64 + mt * 16 + lr;
                int u = 2 * s + lu;
                uint32_t ad = ab + r * 64 + ((u ^ (r & 3)) << 4);
                LDSM4(af[mt][0], af[mt][1], af[mt][2], af[mt][3], ad);
            }
#pragma unroll
            for (int p = 0; p < 2; p++) {
                int r = wn * 32 + p * 16 + lr;
                int u = 2 * s + lu;
                uint32_t bd = ab + 8192 + r * 64 + ((u ^ (r & 3)) << 4);
                uint32_t t0, t1, t2, t3;
                LDSM4(t0, t1, t2, t3, bd);
                bf[p * 2 + 0][0] = t0; bf[p * 2 + 0][1] = t2;
                bf[p * 2 + 1][0] = t1; bf[p * 2 + 1][1] = t3;
            }
#pragma unroll
            for (int mt = 0; mt < 4; mt++)
#pragma unroll
                for (int nt = 0; nt < 4; nt++)
                    MMA16816H(acc[mt][nt], af[mt], bf[nt]);
        }
    }

#pragma unroll
    for (int mt = 0; mt < 4; mt++) {
        int r = m0 + wm * 64 + mt * 16 + (lid >> 2);
#pragma unroll
        for (int nt = 0; nt < 4; nt++) {
            int n = n0 + wn * 32 + nt * 8 + (lid & 3) * 2;
            if (n < N) {
                *(float2*)&C[(size_t)r * N + n] = make_float2(acc[mt][nt][0], acc[mt][nt][1]);
                *(float2*)&C[(size_t)(r + 8) * N + n] = make_float2(acc[mt][nt][2], acc[mt][nt][3]);
            }
        }
    }
}

// ---------------- conv + silu ----------------
__global__ void conv_kernel(const float* __restrict__ zx, const float* __restrict__ cw,
                            const float* __restrict__ cb, float* __restrict__ out) {
    size_t idx = (size_t)blockIdx.x * blockDim.x + threadIdx.x;
    if (idx >= (size_t)BB * LL * CONVDIM) return;
    int c = idx % CONVDIM;
    size_t rest = idx / CONVDIM;
    int t = rest % LL;
    int b = rest / LL;
    float acc = cb[c];
#pragma unroll
    for (int k = 0; k < 4; k++) {
        int tt = t - 3 + k;
        if (tt >= 0)
            acc += zx[((size_t)b * LL + tt) * DPROJ + DIN + c] * cw[k * CONVDIM + c];
    }
    out[idx] = siluf(acc);
}

// ---------------- dt softplus + log dA ----------------
__global__ void dtda_kernel(const float* __restrict__ zx, const float* __restrict__ dtb,
                            const float* __restrict__ alog, float* __restrict__ dtO,
                            float* __restrict__ ldO) {
    size_t idx = (size_t)blockIdx.x * blockDim.x + threadIdx.x;
    if (idx >= (size_t)BB * LL * NH) return;
    int h = idx % NH;
    size_t row = idx / NH;
    float raw = zx[row * DPROJ + (DPROJ - NH) + h] + dtb[h];
    float sp = (raw > 20.f) ? raw : log1pf(expf(raw));
    dtO[idx] = sp;
    ldO[idx] = sp * (-expf(alog[h]));
}

// ---------------- SSD phase A (tensor stages 1-2, SIMT stage 3) ----------------
// smem carve (bytes):
#define SA_OFF_SB 0                       // fp32 sB[64][132]          33792
#define SA_OFF_SXT 33792                  // fp32 sXT[64][68]          17408
#define SA_OFF_HC 51200                   // half hC[64][136]          17408
#define SA_OFF_HB 68608                   // half hB[64][136]          17408
#define SA_OFF_XTH 86016                  // half XTh[64][72]           9216
#define SA_OFF_GM 95232                   // half Gm[64][72]            9216
#define SA_OFF_SCAL 104448                // fp32 sL,sdt,swv,sAt 4*64   1024
#define SA_SMEMB 105472
#define SA_CP 132
#define SA_XP 68

__global__ __launch_bounds__(512) void ssd_a_kernel(const float* __restrict__ conv,
                                                    const float* __restrict__ dtp,
                                                    const float* __restrict__ ldp,
                                                    float* __restrict__ y,
                                                    float* __restrict__ Sd,
                                                    float* __restrict__ Ac,
                                                    float* __restrict__ Atg) {
    const int ck = blockIdx.x & 63;
    const int h = (blockIdx.x >> 6) & 31;
    const int b = blockIdx.x >> 11;
    const size_t t0r = (size_t)b * LL + (size_t)ck * SSD_T;
    const int tid = threadIdx.x;

    extern __shared__ char sabuf[];
    float* sB = (float*)(sabuf + SA_OFF_SB);
    float* sXT = (float*)(sabuf + SA_OFF_SXT);
    __half* hC = (__half*)(sabuf + SA_OFF_HC);
    __half* hB = (__half*)(sabuf + SA_OFF_HB);
    __half* XTh = (__half*)(sabuf + SA_OFF_XTH);
    __half* Gm = (__half*)(sabuf + SA_OFF_GM);
    float* sL = (float*)(sabuf + SA_OFF_SCAL);
    float* sdt = sL + 64;
    float* swv = sdt + 64;
    float* sAt = swv + 64;

    // loads: C and B rows
    for (int q = tid; q < 2048; q += 512) {
        int row = q >> 5, quad = q & 31;
        const float* rowp = conv + (t0r + row) * CONVDIM;
        float4 c4 = *(const float4*)(rowp + 2176 + quad * 4);
        float4 b4 = *(const float4*)(rowp + 2048 + quad * 4);
        *(float4*)&sB[row * SA_CP + quad * 4] = b4;
        *(__half2*)&hC[row * 136 + quad * 4] = __floats2half2_rn(c4.x, c4.y);
        *(__half2*)&hC[row * 136 + quad * 4 + 2] = __floats2half2_rn(c4.z, c4.w);
        *(__half2*)&hB[row * 136 + quad * 4] = __floats2half2_rn(b4.x, b4.y);
        *(__half2*)&hB[row * 136 + quad * 4 + 2] = __floats2half2_rn(b4.z, b4.w);
    }
    // x transposed: sXT[p][u] fp32 and XTh[p][u] fp16
    for (int q = tid; q < 1024; q += 512) {
        int u = q >> 4, quad = q & 15;
        float4 v = *(const float4*)(conv + (t0r + u) * CONVDIM + h * HD + quad * 4);
        sXT[(quad * 4 + 0) * SA_XP + u] = v.x;
        sXT[(quad * 4 + 1) * SA_XP + u] = v.y;
        sXT[(quad * 4 + 2) * SA_XP + u] = v.z;
        sXT[(quad * 4 + 3) * SA_XP + u] = v.w;
        XTh[(quad * 4 + 0) * 72 + u] = __float2half(v.x);
        XTh[(quad * 4 + 1) * 72 + u] = __float2half(v.y);
        XTh[(quad * 4 + 2) * 72 + u] = __float2half(v.z);
        XTh[(quad * 4 + 3) * 72 + u] = __float2half(v.w);
    }
    if (tid < 64) {
        sdt[tid] = dtp[(t0r + tid) * NH + h];
        swv[tid] = ldp[(t0r + tid) * NH + h];
    }
    __syncthreads();
    if (tid < 64) {
        float a = 0.f;
        for (int u = 0; u <= tid; u++) a += swv[u];
        sL[tid] = a;
    }
    __syncthreads();
    if (tid < 64) {
        float l63 = sL[63];
        sAt[tid] = expf(sL[tid]);
        swv[tid] = expf(l63 - sL[tid]) * sdt[tid];
    }
    __syncthreads();

    const int w = tid >> 5, lane = tid & 31;
    const int g = lane >> 2, th = lane & 3;
    const int r0 = (w & 3) * 16, c0 = (w >> 2) * 16;

    // Stage 1: G = C @ B^T (tensor), mask, store fp16
    {
        float ac0[4] = {0.f, 0.f, 0.f, 0.f}, ac1[4] = {0.f, 0.f, 0.f, 0.f};
#pragma unroll
        for (int ks = 0; ks < 8; ks++) {
            uint32_t a[4], bfr[2];
            frag_ldA(a, hC, 136, r0, ks * 16, lane);
            frag_ldB(bfr, hB, 136, c0, ks * 16, lane);
            MMA16816H(ac0, a, bfr);
            frag_ldB(bfr, hB, 136, c0 + 8, ks * 16, lane);
            MMA16816H(ac1, a, bfr);
        }
        int t1 = r0 + g, t2 = r0 + g + 8;
        float lt1 = sL[t1], lt2 = sL[t2];
#pragma unroll
        for (int tl = 0; tl < 2; tl++) {
            float* ac = tl ? ac1 : ac0;
            int u0 = c0 + tl * 8 + th * 2, u1 = u0 + 1;
            float w00 = (u0 <= t1) ? expf(lt1 - sL[u0]) * sdt[u0] : 0.f;
            float w01 = (u1 <= t1) ? expf(lt1 - sL[u1]) * sdt[u1] : 0.f;
            float w10 = (u0 <= t2) ? expf(lt2 - sL[u0]) * sdt[u0] : 0.f;
            float w11 = (u1 <= t2) ? expf(lt2 - sL[u1]) * sdt[u1] : 0.f;
            *(__half2*)&Gm[t1 * 72 + u0] = __floats2half2_rn(ac[0] * w00, ac[1] * w01);
            *(__half2*)&Gm[t2 * 72 + u0] = __floats2half2_rn(ac[2] * w10, ac[3] * w11);
        }
    }
    __syncthreads();

    // Stage 2: Y_intra = G @ X (tensor) -> gmem y
    {
        float ac0[4] = {0.f, 0.f, 0.f, 0.f}, ac1[4] = {0.f, 0.f, 0.f, 0.f};
#pragma unroll
        for (int ks = 0; ks < 4; ks++) {
            uint32_t a[4], bfr[2];
            frag_ldA(a, Gm, 72, r0, ks * 16, lane);
            frag_ldB(bfr, XTh, 72, c0, ks * 16, lane);
            MMA16816H(ac0, a, bfr);
            frag_ldB(bfr, XTh, 72, c0 + 8, ks * 16, lane);
            MMA16816H(ac1, a, bfr);
        }
        int t1 = r0 + g, t2 = r0 + g + 8;
#pragma unroll
        for (int tl = 0; tl < 2; tl++) {
            float* ac = tl ? ac1 : ac0;
            int p = c0 + tl * 8 + th * 2;
            *(float2*)&y[(t0r + t1) * DIN + h * HD + p] = make_float2(ac[0], ac[1]);
            *(float2*)&y[(t0r + t2) * DIN + h * HD + p] = make_float2(ac[2], ac[3]);
        }
    }
    __syncthreads();
    // scale XT by wv (for S_delta)
    for (int q = tid; q < 4096; q += 512) {
        int p = q >> 6, u = q & 63;
        sXT[p * SA_XP + u] *= swv[u];
    }
    __syncthreads();
    // Stage 3 (SIMT fp32, unchanged): S_delta[p][n] = sum_u XTw[p][u] * B[u][n]
    {
        const int pg = tid >> 5, ng = tid & 31;
        float acc[4][4];
#pragma unroll
        for (int i = 0; i < 4; i++)
#pragma unroll
            for (int j = 0; j < 4; j++) acc[i][j] = 0.f;
#pragma unroll 4
        for (int q = 0; q < 16; q++) {
            float4 xv[4], bv[4];
#pragma unroll
            for (int i = 0; i < 4; i++) xv[i] = *(float4*)&sXT[(pg * 4 + i) * SA_XP + q * 4];
#pragma unroll
            for (int r = 0; r < 4; r++) bv[r] = *(float4*)&sB[(q * 4 + r) * SA_CP + ng * 4];
#pragma unroll
            for (int i = 0; i < 4; i++)
#pragma unroll
                for (int j = 0; j < 4; j++) {
                    float bj0 = (&bv[0].x)[j], bj1 = (&bv[1].x)[j], bj2 = (&bv[2].x)[j], bj3 = (&bv[3].x)[j];
                    acc[i][j] = fmaf(xv[i].x, bj0, acc[i][j]);
                    acc[i][j] = fmaf(xv[i].y, bj1, acc[i][j]);
                    acc[i][j] = fmaf(xv[i].z, bj2, acc[i][j]);
                    acc[i][j] = fmaf(xv[i].w, bj3, acc[i][j]);
                }
        }
        size_t sdb = (size_t)blockIdx.x * 8192;
#pragma unroll
        for (int i = 0; i < 4; i++)
            *(float4*)&Sd[sdb + (size_t)(pg * 4 + i) * 128 + ng * 4] =
                make_float4(acc[i][0], acc[i][1], acc[i][2], acc[i][3]);
    }
    if (tid == 0) Ac[blockIdx.x] = expf(sL[63]);
    if (tid < 64) Atg[(size_t)blockIdx.x * 64 + tid] = sAt[tid];
}

// ---------------- SSD phase B: sequential chunk-state combine ----------------
__global__ void ssd_b_kernel(const float* __restrict__ Sd, const float* __restrict__ Ac,
                             float* __restrict__ Ss) {
    const int bh = blockIdx.x;
    const int tid = threadIdx.x;
    float S[16];
#pragma unroll
    for (int j = 0; j < 16; j++) S[j] = 0.f;
    for (int ck = 0; ck < SSD_NCK; ck++) {
        size_t g = (size_t)(bh * SSD_NCK + ck) * 8192 + (size_t)tid * 16;
#pragma unroll
        for (int j = 0; j < 16; j += 4)
            *(float4*)&Ss[g + j] = make_float4(S[j], S[j + 1], S[j + 2], S[j + 3]);
        float a = Ac[bh * SSD_NCK + ck];
#pragma unroll
        for (int j = 0; j < 16; j += 4) {
            float4 d = *(const float4*)&Sd[g + j];
            S[j + 0] = fmaf(S[j + 0], a, d.x);
            S[j + 1] = fmaf(S[j + 1], a, d.y);
            S[j + 2] = fmaf(S[j + 2], a, d.z);
            S[j + 3] = fmaf(S[j + 3], a, d.w);
        }
    }
}

// ---------------- SSD phase C (tensor): y += diag(At) * (C @ S_start) ----------------
#define SCC_OFF_HC 0
#define SCC_OFF_HS 17408
#define SCC_OFF_AT 34816
#define SCC_SMEMB 35072

__global__ __launch_bounds__(512) void ssd_c_kernel(const float* __restrict__ conv,
                                                    const float* __restrict__ Ss,
                                                    const float* __restrict__ Atg,
                                                    float* __restrict__ y) {
    const int ck = blockIdx.x & 63;
    if (ck == 0) return;
    const int h = (blockIdx.x >> 6) & 31;
    const int b = blockIdx.x >> 11;
    const size_t t0r = (size_t)b * LL + (size_t)ck * SSD_T;
    const int tid = threadIdx.x;

    extern __shared__ char scbuf[];
    __half* hC = (__half*)(scbuf + SCC_OFF_HC);
    __half* hS = (__half*)(scbuf + SCC_OFF_HS);
    float* sAt = (float*)(scbuf + SCC_OFF_AT);

    for (int q = tid; q < 2048; q += 512) {
        int row = q >> 5, quad = q & 31;
        float4 c4 = *(const float4*)(conv + (t0r + row) * CONVDIM + 2176 + quad * 4);
        float4 s4 = *(const float4*)&Ss[(size_t)blockIdx.x * 8192 + (size_t)row * 128 + quad * 4];
        *(__half2*)&hC[row * 136 + quad * 4] = __floats2half2_rn(c4.x, c4.y);
        *(__half2*)&hC[row * 136 + quad * 4 + 2] = __floats2half2_rn(c4.z, c4.w);
        *(__half2*)&hS[row * 136 + quad * 4] = __floats2half2_rn(s4.x, s4.y);
        *(__half2*)&hS[row * 136 + quad * 4 + 2] = __floats2half2_rn(s4.z, s4.w);
    }
    if (tid < 64) sAt[tid] = Atg[(size_t)blockIdx.x * 64 + tid];
    __syncthreads();

    const int w = tid >> 5, lane = tid & 31;
    const int g = lane >> 2, th = lane & 3;
    const int r0 = (w & 3) * 16, c0 = (w >> 2) * 16;

    float ac0[4] = {0.f, 0.f, 0.f, 0.f}, ac1[4] = {0.f, 0.f, 0.f, 0.f};
#pragma unroll
    for (int ks = 0; ks < 8; ks++) {
        uint32_t a[4], bfr[2];
        frag_ldA(a, hC, 136, r0, ks * 16, lane);
        frag_ldB(bfr, hS, 136, c0, ks * 16, lane);
        MMA16816H(ac0, a, bfr);
        frag_ldB(bfr, hS, 136, c0 + 8, ks * 16, lane);
        MMA16816H(ac1, a, bfr);
    }
    int t1 = r0 + g, t2 = r0 + g + 8;
    float at1 = sAt[t1], at2 = sAt[t2];
#pragma unroll
    for (int tl = 0; tl < 2; tl++) {
        float* ac = tl ? ac1 : ac0;
        int p = c0 + tl * 8 + th * 2;
        size_t yo1 = (t0r + t1) * DIN + h * HD + p;
        size_t yo2 = (t0r + t2) * DIN + h * HD + p;
        float2 v1 = *(float2*)&y[yo1];
        float2 v2 = *(float2*)&y[yo2];
        v1.x = fmaf(at1, ac[0], v1.x);
        v1.y = fmaf(at1, ac[1], v1.y);
        v2.x = fmaf(at2, ac[2], v2.x);
        v2.y = fmaf(at2, ac[3], v2.y);
        *(float2*)&y[yo1] = v1;
        *(float2*)&y[yo2] = v2;
    }
}

// ---------------- gated rmsnorm (adds D*x) -> fp16 ----------------
__global__ void gnorm_h_kernel(const float* __restrict__ y,
                               const float* __restrict__ conv, const float* __restrict__ Dp,
                               const float* __restrict__ zx, const float* __restrict__ gw,
                               __half* __restrict__ oh) {
    size_t row = blockIdx.x;
    const float* zr = zx + row * DPROJ;
    float v[8];
    float ss = 0.f;
#pragma unroll
    for (int u = 0; u < 8; u++) {
        int i = threadIdx.x + u * 256;
        float xv = conv[row * CONVDIM + i];
        float yv = y[row * DIN + i] + Dp[i >> 6] * xv;
        float z = zr[i];
        float val = yv * siluf(z);
        v[u] = val;
        ss += val * val;
    }
    ss = blockReduceSum(ss);
    float inv = rsqrtf(ss / (float)DIN + 1e-5f);
#pragma unroll
    for (int u = 0; u < 8; u++) {
        int i = threadIdx.x + u * 256;
        oh[row * DIN + i] = __float2half(v[u] * inv * gw[i]);
    }
}

// ---------------- cumsum passes ----------------
__global__ void chunk_sum_kernel(const float* __restrict__ PQ, float* __restrict__ cs) {
    int c = (blockIdx.x & 3) * 256 + threadIdx.x;
    int chunk = (blockIdx.x >> 2) & (NCHUNK - 1);
    int b = blockIdx.x >> 5;
    float s = 0.f;
    size_t base = ((size_t)b * LL + (size_t)chunk * CHL) * (2 * DD) + DD + c;
    for (int l = 0; l < CHL; l++) s += PQ[base + (size_t)l * (2 * DD)];
    cs[((size_t)b * NCHUNK + chunk) * DD + c] = s;
}

__global__ void scan_chunks_kernel(float* __restrict__ cs) {
    int i = blockIdx.x * blockDim.x + threadIdx.x;
    if (i >= BB * DD) return;
    int b = i / DD, c = i % DD;
    float acc = 0.f;
#pragma unroll
    for (int ch = 0; ch < NCHUNK; ch++) {
        size_t o = ((size_t)b * NCHUNK + ch) * DD + c;
        float v = cs[o];
        cs[o] = acc;
        acc += v;
    }
}

__global__ void final_kernel(const float* __restrict__ x, const float* __restrict__ PQ,
                             const float* __restrict__ R,
                             const float* __restrict__ cs, float* __restrict__ out) {
    int c = (blockIdx.x & 3) * 256 + threadIdx.x;
    int chunk = (blockIdx.x >> 2) & (NCHUNK - 1);
    int b = blockIdx.x >> 5;
    float acc = cs[((size_t)b * NCHUNK + chunk) * DD + c];
    size_t rbase = ((size_t)b * LL + (size_t)chunk * CHL) * DD + c;
    size_t pqbase = ((size_t)b * LL + (size_t)chunk * CHL) * (2 * DD) + c;
    for (int l = 0; l < CHL; l++) {
        size_t idx = rbase + (size_t)l * DD;
        size_t pqi = pqbase + (size_t)l * (2 * DD);
        acc += PQ[pqi + DD];
        out[idx] = x[idx] + PQ[pqi] + R[idx] + acc;
    }
}

// ---------------- launch ----------------
extern "C" void kernel_launch(void* const* d_in, const int* in_sizes, int n_in,
                              void* d_out, int out_size) {
    const float* x       = (const float*)d_in[0];
    const float* norm_w  = (const float*)d_in[1];
    const float* in_proj = (const float*)d_in[2];
    const float* conv_W  = (const float*)d_in[3];
    const float* conv_b  = (const float*)d_in[4];
    const float* dt_bias = (const float*)d_in[5];
    const float* A_log   = (const float*)d_in[6];
    const float* Dvec    = (const float*)d_in[7];
    const float* gnorm_w = (const float*)d_in[8];
    const float* zero_W  = (const float*)d_in[9];
    const float* one_W   = (const float*)d_in[10];
    const float* fusion  = (const float*)d_in[11];
    float* out = (float*)d_out;

    float *zx, *conv, *dt, *ld, *y, *PQ, *R, *Wz, *Wc, *cs, *Sd, *Ss, *Ac, *At;
    __half *xnh, *Wpt, *Fzt, *Fot, *Fmt, *zw, *ow, *Wpq, *yh;
    cudaGetSymbolAddress((void**)&zx, g_zx);
    cudaGetSymbolAddress((void**)&conv, g_conv);
    cudaGetSymbolAddress((void**)&dt, g_dt);
    cudaGetSymbolAddress((void**)&ld, g_ld);
    cudaGetSymbolAddress((void**)&y, g_y);
    cudaGetSymbolAddress((void**)&PQ, g_PQ);
    cudaGetSymbolAddress((void**)&R, g_R);
    cudaGetSymbolAddress((void**)&Wz, g_Wz);
    cudaGetSymbolAddress((void**)&Wc, g_Wc);
    cudaGetSymbolAddress((void**)&cs, g_cs);
    cudaGetSymbolAddress((void**)&Sd, g_Sd);
    cudaGetSymbolAddress((void**)&Ss, g_Ss);
    cudaGetSymbolAddress((void**)&Ac, g_Ac);
    cudaGetSymbolAddress((void**)&At, g_At);
    cudaGetSymbolAddress((void**)&xnh, g_xnh);
    cudaGetSymbolAddress((void**)&Wpt, g_Wpt);
    cudaGetSymbolAddress((void**)&Fzt, g_Fzt);
    cudaGetSymbolAddress((void**)&Fot, g_Fot);
    cudaGetSymbolAddress((void**)&Fmt, g_Fmt);
    cudaGetSymbolAddress((void**)&zw, g_zw);
    cudaGetSymbolAddress((void**)&ow, g_ow);
    cudaGetSymbolAddress((void**)&Wpq, g_Wpq);
    cudaGetSymbolAddress((void**)&yh, g_yh);

    const int M = BB * LL;
    cudaFuncSetAttribute(tgemm_kernel, cudaFuncAttributeMaxDynamicSharedMemorySize, TG_SMEM);
    cudaFuncSetAttribute(ssd_a_kernel, cudaFuncAttributeMaxDynamicSharedMemorySize, SA_SMEMB);
    cudaFuncSetAttribute(ssd_c_kernel, cudaFuncAttributeMaxDynamicSharedMemorySize, SCC_SMEMB);

    cudaStream_t s2;
    cudaEvent_t ev0, evA, evB;
    cudaStreamCreateWithFlags(&s2, cudaStreamNonBlocking);
    cudaEventCreateWithFlags(&ev0, cudaEventDisableTiming);
    cudaEventCreateWithFlags(&evA, cudaEventDisableTiming);
    cudaEventCreateWithFlags(&evB, cudaEventDisableTiming);

    dim3 tb(32, 8);

    // ---- main: shared prep ----
    rmsnorm_h_kernel<<<M, 256>>>(x, norm_w, xnh);
    transpose_h_kernel<<<dim3(DD / 32, NPADPROJ / 32), tb>>>(in_proj, DD, DPROJ, Wpt, NPADPROJ);
    transpose_h_kernel<<<dim3(DIN / 32, DD / 32), tb>>>(fusion, DIN, DD, Fmt, DD);
    cudaEventRecord(ev0, 0);

    // ---- main: xBC+dt half of zx, conv, dt/ld ----
    tgemm_kernel<<<dim3((NPADPROJ - 2048) / 128, M / 128), 256, TG_SMEM>>>(xnh, Wpt, zx, M, DPROJ, DD, 2048);
    {
        size_t tot = (size_t)BB * LL * CONVDIM;
        conv_kernel<<<(unsigned)((tot + 255) / 256), 256>>>(zx, conv_W, conv_b, conv);
        size_t tot2 = (size_t)BB * LL * NH;
        dtda_kernel<<<(unsigned)((tot2 + 255) / 256), 256>>>(zx, dt_bias, A_log, dt, ld);
    }
    cudaEventRecord(evA, 0);

    // ---- side: z half of zx, then SSD scan -> gnorm -> R ----
    cudaStreamWaitEvent(s2, ev0, 0);
    tgemm_kernel<<<dim3(2048 / 128, M / 128), 256, TG_SMEM, s2>>>(xnh, Wpt, zx, M, DPROJ, DD, 0);
    cudaStreamWaitEvent(s2, evA, 0);
    ssd_a_kernel<<<NSSD, 512, SA_SMEMB, s2>>>(conv, dt, ld, y, Sd, Ac, At);
    ssd_b_kernel<<<BB * NH, 512, 0, s2>>>(Sd, Ac, Ss);
    ssd_c_kernel<<<NSSD, 512, SCC_SMEMB, s2>>>(conv, Ss, At, y);
    gnorm_h_kernel<<<M, 256, 0, s2>>>(y, conv, Dvec, zx, gnorm_w, yh);
    tgemm_kernel<<<dim3(8, M / 128), 256, TG_SMEM, s2>>>(yh, Fmt, R, M, DD, DIN, 0);
    cudaEventRecord(evB, s2);

    // ---- main (concurrent): combines -> PQ -> cumsum prefix ----
    {
        size_t n = (size_t)DD * DIN;
        tohalf_kernel<<<(unsigned)((n + 255) / 256), 256>>>(zero_W, zw, n);
        tohalf_kernel<<<(unsigned)((n + 255) / 256), 256>>>(one_W, ow, n);
        transpose_h_kernel<<<dim3(DIN / 32, DD / 32), tb>>>(fusion + (size_t)DIN * DD, DIN, DD, Fzt, DD);
        transpose_h_kernel<<<dim3(DIN / 32, DD / 32), tb>>>(fusion + (size_t)2 * DIN * DD, DIN, DD, Fot, DD);
    }
    tgemm_kernel<<<dim3(8, 8), 256, TG_SMEM>>>(zw, Fzt, Wz, DD, DD, DIN, 0);
    tgemm_kernel<<<dim3(8, 8), 256, TG_SMEM>>>(ow, Fot, Wc, DD, DD, DIN, 0);
    transpose_h_kernel<<<dim3(DD / 32, DD / 32), tb>>>(Wz, DD, DD, Wpq, DD);
    transpose_h_kernel<<<dim3(DD / 32, DD / 32), tb>>>(Wc, DD, DD, Wpq + (size_t)DD * DD, DD);
    tgemm_kernel<<<dim3(16, M / 128), 256, TG_SMEM>>>(xnh, Wpq, PQ, M, 2 * DD, DD, 0);
    chunk_sum_kernel<<<BB * NCHUNK * 4, 256>>>(PQ, cs);
    scan_chunks_kernel<<<(BB * DD + 255) / 256, 256>>>(cs);

    // ---- join ----
    cudaStreamWaitEvent(0, evB, 0);
    final_kernel<<<BB * NCHUNK * 4, 256>>>(x, PQ, R, cs, out);

    cudaEventDestroy(ev0);
    cudaEventDestroy(evA);
    cudaEventDestroy(evB);
    cudaStreamDestroy(s2);
}